// round 3
// baseline (speedup 1.0000x reference)
#include <cuda_runtime.h>
#include <math.h>
#include <stdint.h>

#define N_NODES 100000
#define N_EDGES 400000
#define E_TOT   500000
#define N_GRAPHS 2048
#define F_IN 78
#define H1N 10
#define C1  780      // 10*78
#define OUT2 128
#define C2A 130      // +asrc +adst
#define NB_SCAN 98   // ceil(100000/1024)

// ---------------- scratch (device globals; no allocation allowed) -----------
__device__ float g_XAGG[N_NODES * C1];      // 312 MB  per-head weighted x sums
__device__ float g_H1O[N_NODES * C1];       // 312 MB  elu(gat1)
__device__ float g_H2[N_NODES * C2A];       // 52 MB   h1o@W2aug
__device__ float g_ASD1[N_NODES * 2 * H1N]; // [n*20+h]=asrc, [n*20+10+h]=adst
__device__ float g_M1[N_NODES * H1N], g_RD1[N_NODES * H1N];
__device__ float g_AS2[N_NODES], g_AD2[N_NODES], g_M2[N_NODES], g_RD2[N_NODES];
__device__ int   g_DEG[N_NODES], g_INCL[N_NODES], g_BSUM[128], g_BOFF[128];
__device__ int   g_OFF[N_NODES + 1], g_CUR[N_NODES], g_CSRC[E_TOT];
__device__ float g_WATT[F_IN * 2 * H1N];    // folded attention weights
__device__ float g_W2A[C1 * C2A];
__device__ float g_HSUM[N_GRAPHS * OUT2], g_HMAX[N_GRAPHS * OUT2];
__device__ float g_XT[N_GRAPHS * 256], g_XC[N_GRAPHS * 512];
__device__ float g_X1[N_GRAPHS * 1024], g_X2[N_GRAPHS * 256];

// ---------------- CSR build -----------------------------------------------
__global__ void k_initdeg() {
    int i = blockIdx.x * blockDim.x + threadIdx.x;
    if (i < N_NODES) g_DEG[i] = 1;   // self loop
}
__global__ void k_hist(const int* __restrict__ ei) {
    int e = blockIdx.x * blockDim.x + threadIdx.x;
    if (e < N_EDGES) atomicAdd(&g_DEG[ei[N_EDGES + e]], 1);
}
__global__ void k_scan1() {
    __shared__ int sw[32];
    int i = blockIdx.x * 1024 + threadIdx.x;
    int v = (i < N_NODES) ? g_DEG[i] : 0;
    int lane = threadIdx.x & 31, w = threadIdx.x >> 5;
    int x = v;
#pragma unroll
    for (int o = 1; o < 32; o <<= 1) {
        int y = __shfl_up_sync(0xffffffffu, x, o);
        if (lane >= o) x += y;
    }
    if (lane == 31) sw[w] = x;
    __syncthreads();
    if (w == 0) {
        int s = sw[lane];
#pragma unroll
        for (int o = 1; o < 32; o <<= 1) {
            int y = __shfl_up_sync(0xffffffffu, s, o);
            if (lane >= o) s += y;
        }
        sw[lane] = s;
    }
    __syncthreads();
    if (w > 0) x += sw[w - 1];
    if (i < N_NODES) g_INCL[i] = x;
    if (threadIdx.x == 1023) g_BSUM[blockIdx.x] = x;
}
__global__ void k_scan2() {
    __shared__ int sw[4];
    int t = threadIdx.x;            // 128 threads
    int v = (t < NB_SCAN) ? g_BSUM[t] : 0;
    int lane = t & 31, w = t >> 5;
    int x = v;
#pragma unroll
    for (int o = 1; o < 32; o <<= 1) {
        int y = __shfl_up_sync(0xffffffffu, x, o);
        if (lane >= o) x += y;
    }
    if (lane == 31) sw[w] = x;
    __syncthreads();
    int add = 0;
    for (int i = 0; i < w; i++) add += sw[i];
    x += add;
    if (t < NB_SCAN) g_BOFF[t] = x - v;   // exclusive block offsets
}
__global__ void k_scan3() {
    int i = blockIdx.x * blockDim.x + threadIdx.x;
    if (i < N_NODES) {
        int off = g_INCL[i] - g_DEG[i] + g_BOFF[i >> 10];
        g_OFF[i] = off;
        g_CUR[i] = off;
        if (i == 0) g_OFF[N_NODES] = E_TOT;
    }
}
__global__ void k_scatter(const int* __restrict__ ei) {
    int i = blockIdx.x * blockDim.x + threadIdx.x;
    if (i >= E_TOT) return;
    int s, d;
    if (i < N_EDGES) { s = ei[i]; d = ei[N_EDGES + i]; }
    else             { s = d = i - N_EDGES; }
    int pos = atomicAdd(&g_CUR[d], 1);
    g_CSRC[pos] = s;
}

// ---------------- weight prep ------------------------------------------------
// W_att[k, j] = sum_d W1[k, h*78+d] * a[h*78+d]   (j<10: a_src, j>=10: a_dst)
__global__ void k_prep_att(const float* __restrict__ W1, const float* __restrict__ as,
                           const float* __restrict__ ad) {
    int i = blockIdx.x * blockDim.x + threadIdx.x;
    if (i >= F_IN * 2 * H1N) return;
    int k = i / (2 * H1N), j = i - k * (2 * H1N);
    const float* a = (j < H1N) ? (as + j * F_IN) : (ad + (j - H1N) * F_IN);
    int h = (j < H1N) ? j : j - H1N;
    float s = 0.f;
    for (int d = 0; d < F_IN; d++) s += W1[k * C1 + h * F_IN + d] * a[d];
    g_WATT[i] = s;
}
__global__ void k_prep2(const float* __restrict__ W2, const float* __restrict__ as,
                        const float* __restrict__ ad) {
    int i = blockIdx.x * blockDim.x + threadIdx.x;
    if (i >= C1 * C2A) return;
    int k = i / C2A, c = i - k * C2A;
    if (c < OUT2) { g_W2A[i] = W2[k * OUT2 + c]; return; }
    const float* a = (c == OUT2) ? as : ad;
    float s = 0.f;
    for (int d = 0; d < OUT2; d++) s += W2[k * OUT2 + d] * a[d];
    g_W2A[i] = s;
}

// ---------------- attention logits: ASD1 = x @ W_att  [100k, 20] -------------
// one warp per node, 8 nodes per block
__global__ void k_att1(const float* __restrict__ x) {
    __shared__ float sW[F_IN * 2 * H1N];   // 6240 B
    __shared__ float sX[8 * F_IN];
    int tid = threadIdx.x, w = tid >> 5, lane = tid & 31;
    for (int i = tid; i < F_IN * 2 * H1N; i += 256) sW[i] = g_WATT[i];
    int n = blockIdx.x * 8 + w;
    if (n < N_NODES) {
        for (int d = lane; d < F_IN; d += 32) sX[w * F_IN + d] = x[(size_t)n * F_IN + d];
    }
    __syncthreads();
    if (n >= N_NODES || lane >= 2 * H1N) return;
    float s = 0.f;
    for (int d = 0; d < F_IN; d++)
        s = fmaf(sX[w * F_IN + d], sW[d * 2 * H1N + lane], s);
    g_ASD1[n * 2 * H1N + lane] = s;
}

// ---------------- layer 1 softmax ------------------------------------------
__global__ void k_softmax1() {
    int i = blockIdx.x * blockDim.x + threadIdx.x;
    if (i >= N_NODES * H1N) return;
    int n = i / H1N, h = i - n * H1N;
    float adst = g_ASD1[n * 2 * H1N + H1N + h];
    int p0 = g_OFF[n], p1 = g_OFF[n + 1];
    float m = -1e30f;
    for (int p = p0; p < p1; p++) {
        float e = g_ASD1[g_CSRC[p] * 2 * H1N + h] + adst;
        e = e > 0.f ? e : 0.2f * e;
        m = fmaxf(m, e);
    }
    float den = 0.f;
    for (int p = p0; p < p1; p++) {
        float e = g_ASD1[g_CSRC[p] * 2 * H1N + h] + adst;
        e = e > 0.f ? e : 0.2f * e;
        den += expf(e - m);
    }
    g_M1[i] = m;
    g_RD1[i] = 1.f / (den + 1e-16f);
}

// ---------------- layer 1 aggregation in x-space -----------------------------
// xagg[n, h, d] = sum_{src in N(n)} alpha[src->n, h] * x[src, d]
__global__ void k_aggx(const float* __restrict__ x) {
    int n = blockIdx.x, tid = threadIdx.x;
    __shared__ int ssrc[8];
    __shared__ float sal[80];
    __shared__ float sx[8 * F_IN];
    __shared__ float sadst[H1N], sm[H1N], srd[H1N];
    if (tid < H1N) {
        sadst[tid] = g_ASD1[n * 2 * H1N + H1N + tid];
        sm[tid] = g_M1[n * H1N + tid];
        srd[tid] = g_RD1[n * H1N + tid];
    }
    int c0 = tid, c1 = tid + 256, c2 = tid + 512, c3 = tid + 768;
    int h0 = c0 / F_IN, d0 = c0 - h0 * F_IN;
    int h1 = c1 / F_IN, d1 = c1 - h1 * F_IN;
    int h2 = c2 / F_IN, d2 = c2 - h2 * F_IN;
    int h3 = 0, d3 = 0;
    if (c3 < C1) { h3 = c3 / F_IN; d3 = c3 - h3 * F_IN; }
    float a0 = 0.f, a1 = 0.f, a2 = 0.f, a3 = 0.f;
    int p0 = g_OFF[n], p1 = g_OFF[n + 1];
    for (int p = p0; p < p1; p += 8) {
        int cnt = min(8, p1 - p);
        __syncthreads();
        if (tid < cnt) ssrc[tid] = g_CSRC[p + tid];
        __syncthreads();
        for (int i = tid; i < cnt * F_IN; i += 256) {
            int e = i / F_IN, d = i - e * F_IN;
            sx[i] = x[(size_t)ssrc[e] * F_IN + d];
        }
        if (tid < cnt * H1N) {
            int e = tid / H1N, h = tid - e * H1N;
            float ev = g_ASD1[ssrc[e] * 2 * H1N + h] + sadst[h];
            ev = ev > 0.f ? ev : 0.2f * ev;
            sal[tid] = expf(ev - sm[h]) * srd[h];
        }
        __syncthreads();
        for (int e = 0; e < cnt; e++) {
            const float* xe = &sx[e * F_IN];
            const float* ae = &sal[e * H1N];
            a0 = fmaf(ae[h0], xe[d0], a0);
            a1 = fmaf(ae[h1], xe[d1], a1);
            a2 = fmaf(ae[h2], xe[d2], a2);
            if (c3 < C1) a3 = fmaf(ae[h3], xe[d3], a3);
        }
    }
    size_t base = (size_t)n * C1;
    g_XAGG[base + c0] = a0;
    g_XAGG[base + c1] = a1;
    g_XAGG[base + c2] = a2;
    if (c3 < C1) g_XAGG[base + c3] = a3;
}

// ---------------- TF32 tensor-core GEMM: 64x64 block tile, 4 warps ----------
#define PA 20
#define PB 72

__device__ __forceinline__ uint32_t f2tf32(float v) {
    uint32_t u;
    asm("cvt.rna.tf32.f32 %0, %1;" : "=r"(u) : "f"(v));
    return u;
}

// act: 0 none, 1 relu, 2 elu
__global__ void k_mma(const float* __restrict__ A, const float* __restrict__ B,
                      const float* __restrict__ bias, float* __restrict__ C,
                      int M, int K, int N, int lda, int ldb, int ldC, int act) {
    __shared__ float sA[64 * PA];
    __shared__ float sB[16 * PB];
    int t = threadIdx.x;
    int warp = t >> 5, lane = t & 31;
    int g = lane >> 2, tg = lane & 3;
    int wm = warp >> 1, wn = warp & 1;
    int r0 = blockIdx.x * 64;
    int c0 = blockIdx.y * 64;

    float acc[2][4][4];
#pragma unroll
    for (int mi = 0; mi < 2; mi++)
#pragma unroll
        for (int ni = 0; ni < 4; ni++)
#pragma unroll
            for (int r = 0; r < 4; r++) acc[mi][ni][r] = 0.f;

    for (int kt = 0; kt < K; kt += 16) {
#pragma unroll
        for (int i = 0; i < 8; i++) {
            int lin = t + i * 128;
            int row = lin >> 4, col = lin & 15;
            float v = 0.f;
            if (r0 + row < M && kt + col < K) v = A[(size_t)(r0 + row) * lda + kt + col];
            sA[row * PA + col] = __uint_as_float(f2tf32(v));
        }
#pragma unroll
        for (int i = 0; i < 8; i++) {
            int lin = t + i * 128;
            int row = lin >> 6, col = lin & 63;
            float v = 0.f;
            if (kt + row < K && c0 + col < N) v = B[(size_t)(kt + row) * ldb + c0 + col];
            sB[row * PB + col] = __uint_as_float(f2tf32(v));
        }
        __syncthreads();
#pragma unroll
        for (int kk = 0; kk < 16; kk += 8) {
            uint32_t af[2][4];
#pragma unroll
            for (int mi = 0; mi < 2; mi++) {
                int br = wm * 32 + mi * 16;
                af[mi][0] = __float_as_uint(sA[(br + g) * PA + kk + tg]);
                af[mi][1] = __float_as_uint(sA[(br + g + 8) * PA + kk + tg]);
                af[mi][2] = __float_as_uint(sA[(br + g) * PA + kk + tg + 4]);
                af[mi][3] = __float_as_uint(sA[(br + g + 8) * PA + kk + tg + 4]);
            }
            uint32_t bf[4][2];
#pragma unroll
            for (int ni = 0; ni < 4; ni++) {
                int bc = wn * 32 + ni * 8 + g;
                bf[ni][0] = __float_as_uint(sB[(kk + tg) * PB + bc]);
                bf[ni][1] = __float_as_uint(sB[(kk + tg + 4) * PB + bc]);
            }
#pragma unroll
            for (int mi = 0; mi < 2; mi++)
#pragma unroll
                for (int ni = 0; ni < 4; ni++) {
                    asm volatile(
                        "mma.sync.aligned.m16n8k8.row.col.f32.tf32.tf32.f32 "
                        "{%0,%1,%2,%3}, {%4,%5,%6,%7}, {%8,%9}, {%0,%1,%2,%3};\n"
                        : "+f"(acc[mi][ni][0]), "+f"(acc[mi][ni][1]),
                          "+f"(acc[mi][ni][2]), "+f"(acc[mi][ni][3])
                        : "r"(af[mi][0]), "r"(af[mi][1]), "r"(af[mi][2]), "r"(af[mi][3]),
                          "r"(bf[ni][0]), "r"(bf[ni][1]));
                }
        }
        __syncthreads();
    }
#pragma unroll
    for (int mi = 0; mi < 2; mi++) {
#pragma unroll
        for (int ni = 0; ni < 4; ni++) {
            int col = c0 + wn * 32 + ni * 8 + tg * 2;
#pragma unroll
            for (int half = 0; half < 2; half++) {
                int row = r0 + wm * 32 + mi * 16 + g + half * 8;
                if (row < M) {
#pragma unroll
                    for (int q = 0; q < 2; q++) {
                        if (col + q < N) {
                            float v = acc[mi][ni][half * 2 + q] + (bias ? bias[col + q] : 0.f);
                            if (act == 1) v = fmaxf(v, 0.f);
                            else if (act == 2) v = v > 0.f ? v : expm1f(v);
                            C[(size_t)row * ldC + col + q] = v;
                        }
                    }
                }
            }
        }
    }
}

// ---------------- layer 2 softmax / aggregation + readout -------------------
__global__ void k_compact2() {
    int n = blockIdx.x * blockDim.x + threadIdx.x;
    if (n >= N_NODES) return;
    g_AS2[n] = g_H2[(size_t)n * C2A + OUT2];
    g_AD2[n] = g_H2[(size_t)n * C2A + OUT2 + 1];
}
__global__ void k_softmax2() {
    int n = blockIdx.x * blockDim.x + threadIdx.x;
    if (n >= N_NODES) return;
    float adst = g_AD2[n];
    int p0 = g_OFF[n], p1 = g_OFF[n + 1];
    float m = -1e30f;
    for (int p = p0; p < p1; p++) {
        float e = g_AS2[g_CSRC[p]] + adst;
        e = e > 0.f ? e : 0.2f * e;
        m = fmaxf(m, e);
    }
    float den = 0.f;
    for (int p = p0; p < p1; p++) {
        float e = g_AS2[g_CSRC[p]] + adst;
        e = e > 0.f ? e : 0.2f * e;
        den += expf(e - m);
    }
    g_M2[n] = m;
    g_RD2[n] = 1.f / (den + 1e-16f);
}
__global__ void k_zero_readout() {
    int i = blockIdx.x * blockDim.x + threadIdx.x;
    if (i < N_GRAPHS * OUT2) { g_HSUM[i] = 0.f; g_HMAX[i] = 0.f; }
}
__global__ void k_agg2(const float* __restrict__ b2, const float* __restrict__ wg,
                       const float* __restrict__ bg, const int* __restrict__ batch) {
    int n = blockIdx.x, tid = threadIdx.x;
    __shared__ int ssrc[16];
    __shared__ float sal[16];
    __shared__ float red[128];
    float adst = g_AD2[n], m = g_M2[n], rd = g_RD2[n];
    float acc = 0.f;
    int p0 = g_OFF[n], p1 = g_OFF[n + 1];
    for (int p = p0; p < p1; p += 16) {
        int cnt = min(16, p1 - p);
        __syncthreads();
        if (tid < cnt) {
            int s = g_CSRC[p + tid];
            ssrc[tid] = s;
            float ev = g_AS2[s] + adst;
            ev = ev > 0.f ? ev : 0.2f * ev;
            sal[tid] = expf(ev - m) * rd;
        }
        __syncthreads();
        for (int e = 0; e < cnt; e++)
            acc = fmaf(sal[e], g_H2[(size_t)ssrc[e] * C2A + tid], acc);
    }
    float v = fmaxf(acc + b2[tid], 0.f);
    red[tid] = v * wg[tid];
    __syncthreads();
    for (int o = 64; o > 0; o >>= 1) {
        if (tid < o) red[tid] += red[tid + o];
        __syncthreads();
    }
    float w = 1.f / (1.f + expf(-(red[0] + bg[0])));
    int g = batch[n];
    atomicAdd(&g_HSUM[g * OUT2 + tid], v * w);
    atomicMax((int*)&g_HMAX[g * OUT2 + tid], __float_as_int(v));  // v >= 0
}

// ---------------- tail ------------------------------------------------------
__global__ void k_concat() {
    int i = blockIdx.x * blockDim.x + threadIdx.x;
    if (i >= N_GRAPHS * 512) return;
    int g = i / 512, c = i - g * 512;
    float v;
    if (c < 128)      v = g_HSUM[g * 128 + c];
    else if (c < 256) v = g_HMAX[g * 128 + (c - 128)];
    else              v = g_XT[g * 256 + (c - 256)];
    g_XC[i] = v;
}
__global__ void k_out(const float* __restrict__ Wo, const float* __restrict__ bo,
                      float* __restrict__ out) {
    int g = blockIdx.x, lane = threadIdx.x;
    float s = 0.f;
    for (int k = lane; k < 256; k += 32) s += g_X2[g * 256 + k] * Wo[k];
#pragma unroll
    for (int o = 16; o > 0; o >>= 1) s += __shfl_down_sync(0xffffffffu, s, o);
    if (lane == 0) out[g] = s + bo[0];
}

// ---------------- host ------------------------------------------------------
static inline dim3 mma_grid(int M, int N, int Z = 1) {
    return dim3((M + 63) / 64, (N + 63) / 64, Z);
}

extern "C" void kernel_launch(void* const* d_in, const int* in_sizes, int n_in,
                              void* d_out, int out_size) {
    const float* x      = (const float*)d_in[0];
    const int*   ei     = (const int*)d_in[1];
    const int*   batch  = (const int*)d_in[2];
    const float* target = (const float*)d_in[3];
    const float* W1  = (const float*)d_in[4];
    const float* as1 = (const float*)d_in[5];
    const float* ad1 = (const float*)d_in[6];
    const float* b1  = (const float*)d_in[7];
    const float* W2  = (const float*)d_in[8];
    const float* as2 = (const float*)d_in[9];
    const float* ad2 = (const float*)d_in[10];
    const float* b2  = (const float*)d_in[11];
    const float* wg  = (const float*)d_in[12];
    const float* bg  = (const float*)d_in[13];
    const float* Wxt = (const float*)d_in[14];
    const float* bxt = (const float*)d_in[15];
    const float* Wf1 = (const float*)d_in[16];
    const float* bf1 = (const float*)d_in[17];
    const float* Wf2 = (const float*)d_in[18];
    const float* bf2 = (const float*)d_in[19];
    const float* Wo  = (const float*)d_in[20];
    const float* bo  = (const float*)d_in[21];
    float* out = (float*)d_out;

    float *XAGG, *H1O, *H2, *W2A, *XT, *XC, *X1, *X2;
    cudaGetSymbolAddress((void**)&XAGG, g_XAGG);
    cudaGetSymbolAddress((void**)&H1O, g_H1O);
    cudaGetSymbolAddress((void**)&H2,  g_H2);
    cudaGetSymbolAddress((void**)&W2A, g_W2A);
    cudaGetSymbolAddress((void**)&XT,  g_XT);
    cudaGetSymbolAddress((void**)&XC,  g_XC);
    cudaGetSymbolAddress((void**)&X1,  g_X1);
    cudaGetSymbolAddress((void**)&X2,  g_X2);

    // CSR build
    k_initdeg<<<(N_NODES + 255) / 256, 256>>>();
    k_hist<<<(N_EDGES + 255) / 256, 256>>>(ei);
    k_scan1<<<NB_SCAN, 1024>>>();
    k_scan2<<<1, 128>>>();
    k_scan3<<<(N_NODES + 255) / 256, 256>>>();
    k_scatter<<<(E_TOT + 255) / 256, 256>>>(ei);

    // weight prep
    k_prep_att<<<(F_IN * 2 * H1N + 255) / 256, 256>>>(W1, as1, ad1);
    k_prep2<<<(C1 * C2A + 255) / 256, 256>>>(W2, as2, ad2);

    // layer 1: attention logits, softmax, x-space aggregation, per-head GEMM
    k_att1<<<(N_NODES + 7) / 8, 256>>>(x);
    k_softmax1<<<(N_NODES * H1N + 255) / 256, 256>>>();
    k_aggx<<<N_NODES, 256>>>(x);
    // H1O[:, h*78:(h+1)*78] = elu(XAGG[:, h*78:(h+1)*78] @ W1[:, h*78:(h+1)*78] + b1)
    for (int h = 0; h < H1N; h++) {
        k_mma<<<mma_grid(N_NODES, F_IN), 128>>>(
            XAGG + h * F_IN, W1 + h * F_IN, b1 + h * F_IN, H1O + h * F_IN,
            N_NODES, F_IN, F_IN, C1, C1, C1, 2);
    }

    // layer 2: H2 = H1O @ W2A   [100000,780]x[780,130]
    k_mma<<<mma_grid(N_NODES, C2A), 128>>>(H1O, W2A, nullptr, H2,
                                           N_NODES, C1, C2A, C1, C2A, C2A, 0);
    k_compact2<<<(N_NODES + 255) / 256, 256>>>();
    k_softmax2<<<(N_NODES + 255) / 256, 256>>>();
    k_zero_readout<<<(N_GRAPHS * OUT2 + 255) / 256, 256>>>();
    k_agg2<<<N_NODES, 128>>>(b2, wg, bg, batch);

    // tail MLP
    k_mma<<<mma_grid(N_GRAPHS, 256), 128>>>(target, Wxt, bxt, XT,
                                            N_GRAPHS, 1280, 256, 1280, 256, 256, 0);
    k_concat<<<(N_GRAPHS * 512 + 255) / 256, 256>>>();
    k_mma<<<mma_grid(N_GRAPHS, 1024), 128>>>(XC, Wf1, bf1, X1,
                                             N_GRAPHS, 512, 1024, 512, 1024, 1024, 1);
    k_mma<<<mma_grid(N_GRAPHS, 256), 128>>>(X1, Wf2, bf2, X2,
                                            N_GRAPHS, 1024, 256, 1024, 256, 256, 1);
    k_out<<<N_GRAPHS, 32>>>(Wo, bo, out);
}

// round 4
// speedup vs baseline: 1.4451x; 1.4451x over previous
#include <cuda_runtime.h>
#include <math.h>
#include <stdint.h>

#define N_NODES 100000
#define N_EDGES 400000
#define E_TOT   500000
#define N_GRAPHS 2048
#define F_IN 78
#define H1N 10
#define C1  780      // 10*78
#define OUT2 128
#define C2A 130      // +asrc +adst
#define NB_SCAN 98   // ceil(100000/1024)

// ---------------- scratch (device globals; no allocation allowed) -----------
__device__ float g_XAGG[N_NODES * C1];      // 312 MB  per-head weighted x sums
__device__ float g_H1O[N_NODES * C1];       // 312 MB  elu(gat1)
__device__ float g_H2[N_NODES * C2A];       // 52 MB   h1o@W2aug
__device__ float g_ASD1[N_NODES * 2 * H1N]; // [n*20+h]=asrc, [n*20+10+h]=adst
__device__ float g_M1[N_NODES * H1N], g_RD1[N_NODES * H1N];
__device__ float g_AS2[N_NODES], g_AD2[N_NODES], g_M2[N_NODES], g_RD2[N_NODES];
__device__ int   g_DEG[N_NODES], g_INCL[N_NODES], g_BSUM[128], g_BOFF[128];
__device__ int   g_OFF[N_NODES + 1], g_CUR[N_NODES], g_CSRC[E_TOT];
__device__ float g_WATT[F_IN * 2 * H1N];    // folded attention weights
__device__ float g_W2A[C1 * C2A];
__device__ float g_HSUM[N_GRAPHS * OUT2], g_HMAX[N_GRAPHS * OUT2];
__device__ float g_XT[N_GRAPHS * 256], g_XC[N_GRAPHS * 512];
__device__ float g_X1[N_GRAPHS * 1024], g_X2[N_GRAPHS * 256];

// ---------------- CSR build -----------------------------------------------
__global__ void k_initdeg() {
    int i = blockIdx.x * blockDim.x + threadIdx.x;
    if (i < N_NODES) g_DEG[i] = 1;   // self loop
}
__global__ void k_hist(const int* __restrict__ ei) {
    int e = blockIdx.x * blockDim.x + threadIdx.x;
    if (e < N_EDGES) atomicAdd(&g_DEG[ei[N_EDGES + e]], 1);
}
__global__ void k_scan1() {
    __shared__ int sw[32];
    int i = blockIdx.x * 1024 + threadIdx.x;
    int v = (i < N_NODES) ? g_DEG[i] : 0;
    int lane = threadIdx.x & 31, w = threadIdx.x >> 5;
    int x = v;
#pragma unroll
    for (int o = 1; o < 32; o <<= 1) {
        int y = __shfl_up_sync(0xffffffffu, x, o);
        if (lane >= o) x += y;
    }
    if (lane == 31) sw[w] = x;
    __syncthreads();
    if (w == 0) {
        int s = sw[lane];
#pragma unroll
        for (int o = 1; o < 32; o <<= 1) {
            int y = __shfl_up_sync(0xffffffffu, s, o);
            if (lane >= o) s += y;
        }
        sw[lane] = s;
    }
    __syncthreads();
    if (w > 0) x += sw[w - 1];
    if (i < N_NODES) g_INCL[i] = x;
    if (threadIdx.x == 1023) g_BSUM[blockIdx.x] = x;
}
__global__ void k_scan2() {
    __shared__ int sw[4];
    int t = threadIdx.x;            // 128 threads
    int v = (t < NB_SCAN) ? g_BSUM[t] : 0;
    int lane = t & 31, w = t >> 5;
    int x = v;
#pragma unroll
    for (int o = 1; o < 32; o <<= 1) {
        int y = __shfl_up_sync(0xffffffffu, x, o);
        if (lane >= o) x += y;
    }
    if (lane == 31) sw[w] = x;
    __syncthreads();
    int add = 0;
    for (int i = 0; i < w; i++) add += sw[i];
    x += add;
    if (t < NB_SCAN) g_BOFF[t] = x - v;   // exclusive block offsets
}
__global__ void k_scan3() {
    int i = blockIdx.x * blockDim.x + threadIdx.x;
    if (i < N_NODES) {
        int off = g_INCL[i] - g_DEG[i] + g_BOFF[i >> 10];
        g_OFF[i] = off;
        g_CUR[i] = off;
        if (i == 0) g_OFF[N_NODES] = E_TOT;
    }
}
__global__ void k_scatter(const int* __restrict__ ei) {
    int i = blockIdx.x * blockDim.x + threadIdx.x;
    if (i >= E_TOT) return;
    int s, d;
    if (i < N_EDGES) { s = ei[i]; d = ei[N_EDGES + i]; }
    else             { s = d = i - N_EDGES; }
    int pos = atomicAdd(&g_CUR[d], 1);
    g_CSRC[pos] = s;
}

// ---------------- weight prep ------------------------------------------------
__global__ void k_prep_att(const float* __restrict__ W1, const float* __restrict__ as,
                           const float* __restrict__ ad) {
    int i = blockIdx.x * blockDim.x + threadIdx.x;
    if (i >= F_IN * 2 * H1N) return;
    int k = i / (2 * H1N), j = i - k * (2 * H1N);
    const float* a = (j < H1N) ? (as + j * F_IN) : (ad + (j - H1N) * F_IN);
    int h = (j < H1N) ? j : j - H1N;
    float s = 0.f;
    for (int d = 0; d < F_IN; d++) s += W1[k * C1 + h * F_IN + d] * a[d];
    g_WATT[i] = s;
}
__global__ void k_prep2(const float* __restrict__ W2, const float* __restrict__ as,
                        const float* __restrict__ ad) {
    int i = blockIdx.x * blockDim.x + threadIdx.x;
    if (i >= C1 * C2A) return;
    int k = i / C2A, c = i - k * C2A;
    if (c < OUT2) { g_W2A[i] = W2[k * OUT2 + c]; return; }
    const float* a = (c == OUT2) ? as : ad;
    float s = 0.f;
    for (int d = 0; d < OUT2; d++) s += W2[k * OUT2 + d] * a[d];
    g_W2A[i] = s;
}

// ---------------- attention logits: ASD1 = x @ W_att  [100k, 20] -------------
__global__ void k_att1(const float* __restrict__ x) {
    __shared__ float sW[F_IN * 2 * H1N];
    __shared__ float sX[8 * F_IN];
    int tid = threadIdx.x, w = tid >> 5, lane = tid & 31;
    for (int i = tid; i < F_IN * 2 * H1N; i += 256) sW[i] = g_WATT[i];
    int n = blockIdx.x * 8 + w;
    if (n < N_NODES) {
        for (int d = lane; d < F_IN; d += 32) sX[w * F_IN + d] = x[(size_t)n * F_IN + d];
    }
    __syncthreads();
    if (n >= N_NODES || lane >= 2 * H1N) return;
    float s = 0.f;
    for (int d = 0; d < F_IN; d++)
        s = fmaf(sX[w * F_IN + d], sW[d * 2 * H1N + lane], s);
    g_ASD1[n * 2 * H1N + lane] = s;
}

// ---------------- layer 1 softmax ------------------------------------------
__global__ void k_softmax1() {
    int i = blockIdx.x * blockDim.x + threadIdx.x;
    if (i >= N_NODES * H1N) return;
    int n = i / H1N, h = i - n * H1N;
    float adst = g_ASD1[n * 2 * H1N + H1N + h];
    int p0 = g_OFF[n], p1 = g_OFF[n + 1];
    float m = -1e30f;
    for (int p = p0; p < p1; p++) {
        float e = g_ASD1[g_CSRC[p] * 2 * H1N + h] + adst;
        e = e > 0.f ? e : 0.2f * e;
        m = fmaxf(m, e);
    }
    float den = 0.f;
    for (int p = p0; p < p1; p++) {
        float e = g_ASD1[g_CSRC[p] * 2 * H1N + h] + adst;
        e = e > 0.f ? e : 0.2f * e;
        den += expf(e - m);
    }
    g_M1[i] = m;
    g_RD1[i] = 1.f / (den + 1e-16f);
}

// ---------------- layer 1 aggregation in x-space -----------------------------
__global__ void k_aggx(const float* __restrict__ x) {
    int n = blockIdx.x, tid = threadIdx.x;
    __shared__ int ssrc[8];
    __shared__ float sal[80];
    __shared__ float sx[8 * F_IN];
    __shared__ float sadst[H1N], sm[H1N], srd[H1N];
    if (tid < H1N) {
        sadst[tid] = g_ASD1[n * 2 * H1N + H1N + tid];
        sm[tid] = g_M1[n * H1N + tid];
        srd[tid] = g_RD1[n * H1N + tid];
    }
    int c0 = tid, c1 = tid + 256, c2 = tid + 512, c3 = tid + 768;
    int h0 = c0 / F_IN, d0 = c0 - h0 * F_IN;
    int h1 = c1 / F_IN, d1 = c1 - h1 * F_IN;
    int h2 = c2 / F_IN, d2 = c2 - h2 * F_IN;
    int h3 = 0, d3 = 0;
    if (c3 < C1) { h3 = c3 / F_IN; d3 = c3 - h3 * F_IN; }
    float a0 = 0.f, a1 = 0.f, a2 = 0.f, a3 = 0.f;
    int p0 = g_OFF[n], p1 = g_OFF[n + 1];
    for (int p = p0; p < p1; p += 8) {
        int cnt = min(8, p1 - p);
        __syncthreads();
        if (tid < cnt) ssrc[tid] = g_CSRC[p + tid];
        __syncthreads();
        for (int i = tid; i < cnt * F_IN; i += 256) {
            int e = i / F_IN, d = i - e * F_IN;
            sx[i] = x[(size_t)ssrc[e] * F_IN + d];
        }
        if (tid < cnt * H1N) {
            int e = tid / H1N, h = tid - e * H1N;
            float ev = g_ASD1[ssrc[e] * 2 * H1N + h] + sadst[h];
            ev = ev > 0.f ? ev : 0.2f * ev;
            sal[tid] = expf(ev - sm[h]) * srd[h];
        }
        __syncthreads();
        for (int e = 0; e < cnt; e++) {
            const float* xe = &sx[e * F_IN];
            const float* ae = &sal[e * H1N];
            a0 = fmaf(ae[h0], xe[d0], a0);
            a1 = fmaf(ae[h1], xe[d1], a1);
            a2 = fmaf(ae[h2], xe[d2], a2);
            if (c3 < C1) a3 = fmaf(ae[h3], xe[d3], a3);
        }
    }
    size_t base = (size_t)n * C1;
    g_XAGG[base + c0] = a0;
    g_XAGG[base + c1] = a1;
    g_XAGG[base + c2] = a2;
    if (c3 < C1) g_XAGG[base + c3] = a3;
}

// ---------------- TF32 tensor-core GEMM: 64x128 tile, 8 warps, batched -------
#define PA 20    // pitch for 16 k cols
#define PB 136   // pitch for 128 n cols

__device__ __forceinline__ uint32_t f2tf32(float v) {
    uint32_t u;
    asm("cvt.rna.tf32.f32 %0, %1;" : "=r"(u) : "f"(v));
    return u;
}

// act: 0 none, 1 relu, 2 elu. blockIdx.z batches with element strides.
__global__ void k_mma2(const float* __restrict__ A_, const float* __restrict__ B_,
                       const float* __restrict__ bias_, float* __restrict__ C_,
                       int M, int K, int N, int lda, int ldb, int ldC, int act,
                       long long sA_, long long sB_, long long sBias, long long sC_) {
    __shared__ float sA[64 * PA];
    __shared__ float sB[16 * PB];
    const float* A = A_ + (long long)blockIdx.z * sA_;
    const float* B = B_ + (long long)blockIdx.z * sB_;
    const float* bias = bias_ ? bias_ + (long long)blockIdx.z * sBias : nullptr;
    float* C = C_ + (long long)blockIdx.z * sC_;

    int t = threadIdx.x;
    int warp = t >> 5, lane = t & 31;
    int g = lane >> 2, tg = lane & 3;
    int wm = warp >> 2, wn = warp & 3;          // 2x4 warps -> 64x128
    int r0 = blockIdx.x * 64;
    int c0 = blockIdx.y * 128;

    float acc[2][4][4];
#pragma unroll
    for (int mi = 0; mi < 2; mi++)
#pragma unroll
        for (int ni = 0; ni < 4; ni++)
#pragma unroll
            for (int r = 0; r < 4; r++) acc[mi][ni][r] = 0.f;

    for (int kt = 0; kt < K; kt += 16) {
        // A tile 64x16 : 1024 elems, 4 per thread
#pragma unroll
        for (int i = 0; i < 4; i++) {
            int lin = t + i * 256;
            int row = lin >> 4, col = lin & 15;
            float v = 0.f;
            if (r0 + row < M && kt + col < K) v = A[(size_t)(r0 + row) * lda + kt + col];
            sA[row * PA + col] = __uint_as_float(f2tf32(v));
        }
        // B tile 16x128 : 2048 elems, 8 per thread
#pragma unroll
        for (int i = 0; i < 8; i++) {
            int lin = t + i * 256;
            int row = lin >> 7, col = lin & 127;
            float v = 0.f;
            if (kt + row < K && c0 + col < N) v = B[(size_t)(kt + row) * ldb + c0 + col];
            sB[row * PB + col] = __uint_as_float(f2tf32(v));
        }
        __syncthreads();
#pragma unroll
        for (int kk = 0; kk < 16; kk += 8) {
            uint32_t af[2][4];
#pragma unroll
            for (int mi = 0; mi < 2; mi++) {
                int br = wm * 32 + mi * 16;
                af[mi][0] = __float_as_uint(sA[(br + g) * PA + kk + tg]);
                af[mi][1] = __float_as_uint(sA[(br + g + 8) * PA + kk + tg]);
                af[mi][2] = __float_as_uint(sA[(br + g) * PA + kk + tg + 4]);
                af[mi][3] = __float_as_uint(sA[(br + g + 8) * PA + kk + tg + 4]);
            }
            uint32_t bf[4][2];
#pragma unroll
            for (int ni = 0; ni < 4; ni++) {
                int bc = wn * 32 + ni * 8 + g;
                bf[ni][0] = __float_as_uint(sB[(kk + tg) * PB + bc]);
                bf[ni][1] = __float_as_uint(sB[(kk + tg + 4) * PB + bc]);
            }
#pragma unroll
            for (int mi = 0; mi < 2; mi++)
#pragma unroll
                for (int ni = 0; ni < 4; ni++) {
                    asm volatile(
                        "mma.sync.aligned.m16n8k8.row.col.f32.tf32.tf32.f32 "
                        "{%0,%1,%2,%3}, {%4,%5,%6,%7}, {%8,%9}, {%0,%1,%2,%3};\n"
                        : "+f"(acc[mi][ni][0]), "+f"(acc[mi][ni][1]),
                          "+f"(acc[mi][ni][2]), "+f"(acc[mi][ni][3])
                        : "r"(af[mi][0]), "r"(af[mi][1]), "r"(af[mi][2]), "r"(af[mi][3]),
                          "r"(bf[ni][0]), "r"(bf[ni][1]));
                }
        }
        __syncthreads();
    }
#pragma unroll
    for (int mi = 0; mi < 2; mi++) {
#pragma unroll
        for (int ni = 0; ni < 4; ni++) {
            int col = c0 + wn * 32 + ni * 8 + tg * 2;
#pragma unroll
            for (int half = 0; half < 2; half++) {
                int row = r0 + wm * 32 + mi * 16 + g + half * 8;
                if (row < M) {
#pragma unroll
                    for (int q = 0; q < 2; q++) {
                        if (col + q < N) {
                            float v = acc[mi][ni][half * 2 + q] + (bias ? bias[col + q] : 0.f);
                            if (act == 1) v = fmaxf(v, 0.f);
                            else if (act == 2) v = v > 0.f ? v : expm1f(v);
                            C[(size_t)row * ldC + col + q] = v;
                        }
                    }
                }
            }
        }
    }
}

// ---------------- layer 2 softmax / aggregation + readout -------------------
__global__ void k_compact2() {
    int n = blockIdx.x * blockDim.x + threadIdx.x;
    if (n >= N_NODES) return;
    g_AS2[n] = g_H2[(size_t)n * C2A + OUT2];
    g_AD2[n] = g_H2[(size_t)n * C2A + OUT2 + 1];
}
__global__ void k_softmax2() {
    int n = blockIdx.x * blockDim.x + threadIdx.x;
    if (n >= N_NODES) return;
    float adst = g_AD2[n];
    int p0 = g_OFF[n], p1 = g_OFF[n + 1];
    float m = -1e30f;
    for (int p = p0; p < p1; p++) {
        float e = g_AS2[g_CSRC[p]] + adst;
        e = e > 0.f ? e : 0.2f * e;
        m = fmaxf(m, e);
    }
    float den = 0.f;
    for (int p = p0; p < p1; p++) {
        float e = g_AS2[g_CSRC[p]] + adst;
        e = e > 0.f ? e : 0.2f * e;
        den += expf(e - m);
    }
    g_M2[n] = m;
    g_RD2[n] = 1.f / (den + 1e-16f);
}
__global__ void k_zero_readout() {
    int i = blockIdx.x * blockDim.x + threadIdx.x;
    if (i < N_GRAPHS * OUT2) { g_HSUM[i] = 0.f; g_HMAX[i] = 0.f; }
}
__global__ void k_agg2(const float* __restrict__ b2, const float* __restrict__ wg,
                       const float* __restrict__ bg, const int* __restrict__ batch) {
    int n = blockIdx.x, tid = threadIdx.x;
    __shared__ int ssrc[16];
    __shared__ float sal[16];
    __shared__ float red[128];
    float adst = g_AD2[n], m = g_M2[n], rd = g_RD2[n];
    float acc = 0.f;
    int p0 = g_OFF[n], p1 = g_OFF[n + 1];
    for (int p = p0; p < p1; p += 16) {
        int cnt = min(16, p1 - p);
        __syncthreads();
        if (tid < cnt) {
            int s = g_CSRC[p + tid];
            ssrc[tid] = s;
            float ev = g_AS2[s] + adst;
            ev = ev > 0.f ? ev : 0.2f * ev;
            sal[tid] = expf(ev - m) * rd;
        }
        __syncthreads();
        for (int e = 0; e < cnt; e++)
            acc = fmaf(sal[e], g_H2[(size_t)ssrc[e] * C2A + tid], acc);
    }
    float v = fmaxf(acc + b2[tid], 0.f);
    red[tid] = v * wg[tid];
    __syncthreads();
    for (int o = 64; o > 0; o >>= 1) {
        if (tid < o) red[tid] += red[tid + o];
        __syncthreads();
    }
    float w = 1.f / (1.f + expf(-(red[0] + bg[0])));
    int g = batch[n];
    atomicAdd(&g_HSUM[g * OUT2 + tid], v * w);
    atomicMax((int*)&g_HMAX[g * OUT2 + tid], __float_as_int(v));  // v >= 0
}

// ---------------- tail ------------------------------------------------------
__global__ void k_concat() {
    int i = blockIdx.x * blockDim.x + threadIdx.x;
    if (i >= N_GRAPHS * 512) return;
    int g = i / 512, c = i - g * 512;
    float v;
    if (c < 128)      v = g_HSUM[g * 128 + c];
    else if (c < 256) v = g_HMAX[g * 128 + (c - 128)];
    else              v = g_XT[g * 256 + (c - 256)];
    g_XC[i] = v;
}
__global__ void k_out(const float* __restrict__ Wo, const float* __restrict__ bo,
                      float* __restrict__ out) {
    int g = blockIdx.x, lane = threadIdx.x;
    float s = 0.f;
    for (int k = lane; k < 256; k += 32) s += g_X2[g * 256 + k] * Wo[k];
#pragma unroll
    for (int o = 16; o > 0; o >>= 1) s += __shfl_down_sync(0xffffffffu, s, o);
    if (lane == 0) out[g] = s + bo[0];
}

// ---------------- host ------------------------------------------------------
static inline dim3 mma2_grid(int M, int N, int Z = 1) {
    return dim3((M + 63) / 64, (N + 127) / 128, Z);
}

extern "C" void kernel_launch(void* const* d_in, const int* in_sizes, int n_in,
                              void* d_out, int out_size) {
    const float* x      = (const float*)d_in[0];
    const int*   ei     = (const int*)d_in[1];
    const int*   batch  = (const int*)d_in[2];
    const float* target = (const float*)d_in[3];
    const float* W1  = (const float*)d_in[4];
    const float* as1 = (const float*)d_in[5];
    const float* ad1 = (const float*)d_in[6];
    const float* b1  = (const float*)d_in[7];
    const float* W2  = (const float*)d_in[8];
    const float* as2 = (const float*)d_in[9];
    const float* ad2 = (const float*)d_in[10];
    const float* b2  = (const float*)d_in[11];
    const float* wg  = (const float*)d_in[12];
    const float* bg  = (const float*)d_in[13];
    const float* Wxt = (const float*)d_in[14];
    const float* bxt = (const float*)d_in[15];
    const float* Wf1 = (const float*)d_in[16];
    const float* bf1 = (const float*)d_in[17];
    const float* Wf2 = (const float*)d_in[18];
    const float* bf2 = (const float*)d_in[19];
    const float* Wo  = (const float*)d_in[20];
    const float* bo  = (const float*)d_in[21];
    float* out = (float*)d_out;

    float *XAGG, *H1O, *H2, *W2A, *XT, *XC, *X1, *X2;
    cudaGetSymbolAddress((void**)&XAGG, g_XAGG);
    cudaGetSymbolAddress((void**)&H1O, g_H1O);
    cudaGetSymbolAddress((void**)&H2,  g_H2);
    cudaGetSymbolAddress((void**)&W2A, g_W2A);
    cudaGetSymbolAddress((void**)&XT,  g_XT);
    cudaGetSymbolAddress((void**)&XC,  g_XC);
    cudaGetSymbolAddress((void**)&X1,  g_X1);
    cudaGetSymbolAddress((void**)&X2,  g_X2);

    // CSR build
    k_initdeg<<<(N_NODES + 255) / 256, 256>>>();
    k_hist<<<(N_EDGES + 255) / 256, 256>>>(ei);
    k_scan1<<<NB_SCAN, 1024>>>();
    k_scan2<<<1, 128>>>();
    k_scan3<<<(N_NODES + 255) / 256, 256>>>();
    k_scatter<<<(E_TOT + 255) / 256, 256>>>(ei);

    // weight prep
    k_prep_att<<<(F_IN * 2 * H1N + 255) / 256, 256>>>(W1, as1, ad1);
    k_prep2<<<(C1 * C2A + 255) / 256, 256>>>(W2, as2, ad2);

    // layer 1: logits -> softmax -> x-space aggregation -> ONE batched GEMM
    k_att1<<<(N_NODES + 7) / 8, 256>>>(x);
    k_softmax1<<<(N_NODES * H1N + 255) / 256, 256>>>();
    k_aggx<<<N_NODES, 256>>>(x);
    // per head h: H1O[:, h*78:(h+1)*78] = elu(XAGG[:, h*78:..] @ W1[:, h*78:..] + b1[h*78:..])
    k_mma2<<<mma2_grid(N_NODES, F_IN, H1N), 256>>>(
        XAGG, W1, b1, H1O, N_NODES, F_IN, F_IN, C1, C1, C1, 2,
        F_IN, F_IN, F_IN, F_IN);

    // layer 2: H2 = H1O @ W2A   [100000,780]x[780,130]
    k_mma2<<<mma2_grid(N_NODES, C2A), 256>>>(H1O, W2A, nullptr, H2,
                                             N_NODES, C1, C2A, C1, C2A, C2A, 0,
                                             0, 0, 0, 0);
    k_compact2<<<(N_NODES + 255) / 256, 256>>>();
    k_softmax2<<<(N_NODES + 255) / 256, 256>>>();
    k_zero_readout<<<(N_GRAPHS * OUT2 + 255) / 256, 256>>>();
    k_agg2<<<N_NODES, 128>>>(b2, wg, bg, batch);

    // tail MLP
    k_mma2<<<mma2_grid(N_GRAPHS, 256), 256>>>(target, Wxt, bxt, XT,
                                              N_GRAPHS, 1280, 256, 1280, 256, 256, 0,
                                              0, 0, 0, 0);
    k_concat<<<(N_GRAPHS * 512 + 255) / 256, 256>>>();
    k_mma2<<<mma2_grid(N_GRAPHS, 1024), 256>>>(XC, Wf1, bf1, X1,
                                               N_GRAPHS, 512, 1024, 512, 1024, 1024, 1,
                                               0, 0, 0, 0);
    k_mma2<<<mma2_grid(N_GRAPHS, 256), 256>>>(X1, Wf2, bf2, X2,
                                              N_GRAPHS, 1024, 256, 1024, 256, 256, 1,
                                              0, 0, 0, 0);
    k_out<<<N_GRAPHS, 32>>>(Wo, bo, out);
}

// round 5
// speedup vs baseline: 2.0702x; 1.4326x over previous
#include <cuda_runtime.h>
#include <math.h>
#include <stdint.h>

#define N_NODES 100000
#define N_EDGES 400000
#define E_TOT   500000
#define N_GRAPHS 2048
#define F_IN 78
#define H1N 10
#define C1  780      // 10*78
#define OUT2 128
#define NB_SCAN 98   // ceil(100000/1024)

// ---------------- scratch (device globals; no allocation allowed) -----------
__device__ float g_XAGG[N_NODES * C1];      // 312 MB  per-head weighted x sums
__device__ float g_H1O[N_NODES * C1];       // 312 MB  elu(gat1)
__device__ float g_H2[N_NODES * OUT2];      // 51 MB
__device__ float g_ASD1[N_NODES * 2 * H1N];
__device__ float g_AS2[N_NODES], g_AD2[N_NODES];
__device__ int   g_DEG[N_NODES], g_INCL[N_NODES], g_BSUM[128], g_BOFF[128];
__device__ int   g_OFF[N_NODES + 1], g_CUR[N_NODES], g_CSRC[E_TOT];
__device__ float g_WATT[F_IN * 2 * H1N];
__device__ float g_W2AS[C1], g_W2AD[C1];    // W2 @ a_src2 / a_dst2
__device__ float g_HSUM[N_GRAPHS * OUT2], g_HMAX[N_GRAPHS * OUT2];
__device__ float g_XT[N_GRAPHS * 256], g_XC[N_GRAPHS * 512];
__device__ float g_X1[N_GRAPHS * 1024], g_X2[N_GRAPHS * 256];

// ---------------- CSR build -----------------------------------------------
__global__ void k_initdeg() {
    int i = blockIdx.x * blockDim.x + threadIdx.x;
    if (i < N_NODES) g_DEG[i] = 1;
}
__global__ void k_hist(const int* __restrict__ ei) {
    int e = blockIdx.x * blockDim.x + threadIdx.x;
    if (e < N_EDGES) atomicAdd(&g_DEG[ei[N_EDGES + e]], 1);
}
__global__ void k_scan1() {
    __shared__ int sw[32];
    int i = blockIdx.x * 1024 + threadIdx.x;
    int v = (i < N_NODES) ? g_DEG[i] : 0;
    int lane = threadIdx.x & 31, w = threadIdx.x >> 5;
    int x = v;
#pragma unroll
    for (int o = 1; o < 32; o <<= 1) {
        int y = __shfl_up_sync(0xffffffffu, x, o);
        if (lane >= o) x += y;
    }
    if (lane == 31) sw[w] = x;
    __syncthreads();
    if (w == 0) {
        int s = sw[lane];
#pragma unroll
        for (int o = 1; o < 32; o <<= 1) {
            int y = __shfl_up_sync(0xffffffffu, s, o);
            if (lane >= o) s += y;
        }
        sw[lane] = s;
    }
    __syncthreads();
    if (w > 0) x += sw[w - 1];
    if (i < N_NODES) g_INCL[i] = x;
    if (threadIdx.x == 1023) g_BSUM[blockIdx.x] = x;
}
__global__ void k_scan2() {
    __shared__ int sw[4];
    int t = threadIdx.x;
    int v = (t < NB_SCAN) ? g_BSUM[t] : 0;
    int lane = t & 31, w = t >> 5;
    int x = v;
#pragma unroll
    for (int o = 1; o < 32; o <<= 1) {
        int y = __shfl_up_sync(0xffffffffu, x, o);
        if (lane >= o) x += y;
    }
    if (lane == 31) sw[w] = x;
    __syncthreads();
    int add = 0;
    for (int i = 0; i < w; i++) add += sw[i];
    x += add;
    if (t < NB_SCAN) g_BOFF[t] = x - v;
}
__global__ void k_scan3() {
    int i = blockIdx.x * blockDim.x + threadIdx.x;
    if (i < N_NODES) {
        int off = g_INCL[i] - g_DEG[i] + g_BOFF[i >> 10];
        g_OFF[i] = off;
        g_CUR[i] = off;
        if (i == 0) g_OFF[N_NODES] = E_TOT;
    }
}
__global__ void k_scatter(const int* __restrict__ ei) {
    int i = blockIdx.x * blockDim.x + threadIdx.x;
    if (i >= E_TOT) return;
    int s, d;
    if (i < N_EDGES) { s = ei[i]; d = ei[N_EDGES + i]; }
    else             { s = d = i - N_EDGES; }
    int pos = atomicAdd(&g_CUR[d], 1);
    g_CSRC[pos] = s;
}

// ---------------- zero-init (readout accumulators + att2 accumulators) ------
__global__ void k_zero() {
    int i = blockIdx.x * blockDim.x + threadIdx.x;
    if (i < N_GRAPHS * OUT2) { g_HSUM[i] = 0.f; g_HMAX[i] = 0.f; }
    if (i < N_NODES) { g_AS2[i] = 0.f; g_AD2[i] = 0.f; }
}

// ---------------- weight prep ------------------------------------------------
__global__ void k_prep_att(const float* __restrict__ W1, const float* __restrict__ as,
                           const float* __restrict__ ad) {
    int i = blockIdx.x * blockDim.x + threadIdx.x;
    if (i >= F_IN * 2 * H1N) return;
    int k = i / (2 * H1N), j = i - k * (2 * H1N);
    const float* a = (j < H1N) ? (as + j * F_IN) : (ad + (j - H1N) * F_IN);
    int h = (j < H1N) ? j : j - H1N;
    float s = 0.f;
    for (int d = 0; d < F_IN; d++) s += W1[k * C1 + h * F_IN + d] * a[d];
    g_WATT[i] = s;
}
// w2as[k] = sum_d W2[k,d]*as2[d]; w2ad likewise
__global__ void k_prep2v(const float* __restrict__ W2, const float* __restrict__ as,
                         const float* __restrict__ ad) {
    int k = blockIdx.x * blockDim.x + threadIdx.x;
    if (k >= C1) return;
    float s = 0.f, t = 0.f;
    for (int d = 0; d < OUT2; d++) {
        float w = W2[k * OUT2 + d];
        s = fmaf(w, as[d], s);
        t = fmaf(w, ad[d], t);
    }
    g_W2AS[k] = s;
    g_W2AD[k] = t;
}

// ---------------- attention logits: ASD1 = x @ W_att  [100k, 20] -------------
__global__ void k_att1(const float* __restrict__ x) {
    __shared__ float sW[F_IN * 2 * H1N];
    __shared__ float sX[8 * F_IN];
    int tid = threadIdx.x, w = tid >> 5, lane = tid & 31;
    for (int i = tid; i < F_IN * 2 * H1N; i += 256) sW[i] = g_WATT[i];
    int n = blockIdx.x * 8 + w;
    if (n < N_NODES) {
        for (int d = lane; d < F_IN; d += 32) sX[w * F_IN + d] = x[(size_t)n * F_IN + d];
    }
    __syncthreads();
    if (n >= N_NODES || lane >= 2 * H1N) return;
    float s = 0.f;
    for (int d = 0; d < F_IN; d++)
        s = fmaf(sX[w * F_IN + d], sW[d * 2 * H1N + lane], s);
    g_ASD1[n * 2 * H1N + lane] = s;
}

// ---------------- layer 1: fused softmax + x-space aggregation (warp/node) --
__global__ void k_aggx_w(const float* __restrict__ x) {
    int n = blockIdx.x * 8 + (threadIdx.x >> 5);
    if (n >= N_NODES) return;
    int lane = threadIdx.x & 31;
    int p0 = g_OFF[n], p1 = g_OFF[n + 1];

    float adst = (lane < H1N) ? g_ASD1[n * 2 * H1N + H1N + lane] : 0.f;
    // pass 1: max
    float m = -1e30f;
    for (int p = p0; p < p1; p++) {
        int s = g_CSRC[p];
        if (lane < H1N) {
            float e = g_ASD1[s * 2 * H1N + lane] + adst;
            e = e > 0.f ? e : 0.2f * e;
            m = fmaxf(m, e);
        }
    }
    // pass 2: denom
    float den = 0.f;
    for (int p = p0; p < p1; p++) {
        int s = g_CSRC[p];
        if (lane < H1N) {
            float e = g_ASD1[s * 2 * H1N + lane] + adst;
            e = e > 0.f ? e : 0.2f * e;
            den += expf(e - m);
        }
    }
    float rd = 1.f / (den + 1e-16f);
    // pass 3: aggregate
    float acc[H1N][3];
#pragma unroll
    for (int h = 0; h < H1N; h++) { acc[h][0] = 0.f; acc[h][1] = 0.f; acc[h][2] = 0.f; }
    for (int p = p0; p < p1; p++) {
        int s = g_CSRC[p];
        float al = 0.f;
        if (lane < H1N) {
            float e = g_ASD1[s * 2 * H1N + lane] + adst;
            e = e > 0.f ? e : 0.2f * e;
            al = expf(e - m) * rd;
        }
        const float* xr = &x[(size_t)s * F_IN];
        float xv0 = xr[lane];
        float xv1 = xr[32 + lane];
        float xv2 = (lane < F_IN - 64) ? xr[64 + lane] : 0.f;
#pragma unroll
        for (int h = 0; h < H1N; h++) {
            float a = __shfl_sync(0xffffffffu, al, h);
            acc[h][0] = fmaf(a, xv0, acc[h][0]);
            acc[h][1] = fmaf(a, xv1, acc[h][1]);
            acc[h][2] = fmaf(a, xv2, acc[h][2]);
        }
    }
    size_t base = (size_t)n * C1;
#pragma unroll
    for (int h = 0; h < H1N; h++) {
        g_XAGG[base + h * F_IN + lane] = acc[h][0];
        g_XAGG[base + h * F_IN + 32 + lane] = acc[h][1];
        if (lane < F_IN - 64) g_XAGG[base + h * F_IN + 64 + lane] = acc[h][2];
    }
}

// ---------------- TF32 tensor-core GEMM: 64x128 tile, 8 warps, batched -------
// Optional epilogue: accumulate per-row dots with att_s/att_d into outAS/outAD.
#define PAp 20
#define PBp 136

__device__ __forceinline__ uint32_t f2tf32(float v) {
    uint32_t u;
    asm("cvt.rna.tf32.f32 %0, %1;" : "=r"(u) : "f"(v));
    return u;
}

__global__ void k_mma2(const float* __restrict__ A_, const float* __restrict__ B_,
                       const float* __restrict__ bias_, float* __restrict__ C_,
                       int M, int K, int N, int lda, int ldb, int ldC, int act,
                       long long stA, long long stB, long long stBias, long long stC,
                       const float* __restrict__ attS_, const float* __restrict__ attD_,
                       long long stAtt, float* __restrict__ outAS, float* __restrict__ outAD) {
    __shared__ float sA[64 * PAp];
    __shared__ float sB[16 * PBp];
    const float* A = A_ + (long long)blockIdx.z * stA;
    const float* B = B_ + (long long)blockIdx.z * stB;
    const float* bias = bias_ ? bias_ + (long long)blockIdx.z * stBias : nullptr;
    float* C = C_ + (long long)blockIdx.z * stC;
    const float* attS = attS_ ? attS_ + (long long)blockIdx.z * stAtt : nullptr;
    const float* attD = attD_ ? attD_ + (long long)blockIdx.z * stAtt : nullptr;

    int t = threadIdx.x;
    int warp = t >> 5, lane = t & 31;
    int g = lane >> 2, tg = lane & 3;
    int wm = warp >> 2, wn = warp & 3;
    int r0 = blockIdx.x * 64;
    int c0 = blockIdx.y * 128;

    float acc[2][4][4];
#pragma unroll
    for (int mi = 0; mi < 2; mi++)
#pragma unroll
        for (int ni = 0; ni < 4; ni++)
#pragma unroll
            for (int r = 0; r < 4; r++) acc[mi][ni][r] = 0.f;

    for (int kt = 0; kt < K; kt += 16) {
#pragma unroll
        for (int i = 0; i < 4; i++) {
            int lin = t + i * 256;
            int row = lin >> 4, col = lin & 15;
            float v = 0.f;
            if (r0 + row < M && kt + col < K) v = A[(size_t)(r0 + row) * lda + kt + col];
            sA[row * PAp + col] = __uint_as_float(f2tf32(v));
        }
#pragma unroll
        for (int i = 0; i < 8; i++) {
            int lin = t + i * 256;
            int row = lin >> 7, col = lin & 127;
            float v = 0.f;
            if (kt + row < K && c0 + col < N) v = B[(size_t)(kt + row) * ldb + c0 + col];
            sB[row * PBp + col] = __uint_as_float(f2tf32(v));
        }
        __syncthreads();
#pragma unroll
        for (int kk = 0; kk < 16; kk += 8) {
            uint32_t af[2][4];
#pragma unroll
            for (int mi = 0; mi < 2; mi++) {
                int br = wm * 32 + mi * 16;
                af[mi][0] = __float_as_uint(sA[(br + g) * PAp + kk + tg]);
                af[mi][1] = __float_as_uint(sA[(br + g + 8) * PAp + kk + tg]);
                af[mi][2] = __float_as_uint(sA[(br + g) * PAp + kk + tg + 4]);
                af[mi][3] = __float_as_uint(sA[(br + g + 8) * PAp + kk + tg + 4]);
            }
            uint32_t bf[4][2];
#pragma unroll
            for (int ni = 0; ni < 4; ni++) {
                int bc = wn * 32 + ni * 8 + g;
                bf[ni][0] = __float_as_uint(sB[(kk + tg) * PBp + bc]);
                bf[ni][1] = __float_as_uint(sB[(kk + tg + 4) * PBp + bc]);
            }
#pragma unroll
            for (int mi = 0; mi < 2; mi++)
#pragma unroll
                for (int ni = 0; ni < 4; ni++) {
                    asm volatile(
                        "mma.sync.aligned.m16n8k8.row.col.f32.tf32.tf32.f32 "
                        "{%0,%1,%2,%3}, {%4,%5,%6,%7}, {%8,%9}, {%0,%1,%2,%3};\n"
                        : "+f"(acc[mi][ni][0]), "+f"(acc[mi][ni][1]),
                          "+f"(acc[mi][ni][2]), "+f"(acc[mi][ni][3])
                        : "r"(af[mi][0]), "r"(af[mi][1]), "r"(af[mi][2]), "r"(af[mi][3]),
                          "r"(bf[ni][0]), "r"(bf[ni][1]));
                }
        }
        __syncthreads();
    }
    // epilogue
#pragma unroll
    for (int mi = 0; mi < 2; mi++) {
#pragma unroll
        for (int half = 0; half < 2; half++) {
            int row = r0 + wm * 32 + mi * 16 + g + half * 8;
            float ps = 0.f, pd = 0.f;
#pragma unroll
            for (int ni = 0; ni < 4; ni++) {
                int col = c0 + wn * 32 + ni * 8 + tg * 2;
#pragma unroll
                for (int q = 0; q < 2; q++) {
                    if (row < M && col + q < N) {
                        float v = acc[mi][ni][half * 2 + q] + (bias ? bias[col + q] : 0.f);
                        if (act == 1) v = fmaxf(v, 0.f);
                        else if (act == 2) v = v > 0.f ? v : expm1f(v);
                        C[(size_t)row * ldC + col + q] = v;
                        if (attS) {
                            ps = fmaf(v, attS[col + q], ps);
                            pd = fmaf(v, attD[col + q], pd);
                        }
                    }
                }
            }
            if (attS) {
                // reduce over tg lanes (same row, different cols)
                ps += __shfl_xor_sync(0xffffffffu, ps, 1);
                ps += __shfl_xor_sync(0xffffffffu, ps, 2);
                pd += __shfl_xor_sync(0xffffffffu, pd, 1);
                pd += __shfl_xor_sync(0xffffffffu, pd, 2);
                if (tg == 0 && row < M) {
                    atomicAdd(&outAS[row], ps);
                    atomicAdd(&outAD[row], pd);
                }
            }
        }
    }
}

// ---------------- layer 2: fused softmax + aggregation + readout (warp/node)-
__global__ void k_agg2_w(const float* __restrict__ b2, const float* __restrict__ wg,
                         const float* __restrict__ bg, const int* __restrict__ batch) {
    int n = blockIdx.x * 8 + (threadIdx.x >> 5);
    if (n >= N_NODES) return;
    int lane = threadIdx.x & 31;
    int p0 = g_OFF[n], p1 = g_OFF[n + 1];
    float adst = g_AD2[n];
    // softmax stats (all lanes redundantly; broadcast loads)
    float m = -1e30f;
    for (int p = p0; p < p1; p++) {
        float e = g_AS2[g_CSRC[p]] + adst;
        e = e > 0.f ? e : 0.2f * e;
        m = fmaxf(m, e);
    }
    float den = 0.f;
    for (int p = p0; p < p1; p++) {
        float e = g_AS2[g_CSRC[p]] + adst;
        e = e > 0.f ? e : 0.2f * e;
        den += expf(e - m);
    }
    float rd = 1.f / (den + 1e-16f);
    float a0 = 0.f, a1 = 0.f, a2 = 0.f, a3 = 0.f;
    for (int p = p0; p < p1; p++) {
        int s = g_CSRC[p];
        float e = g_AS2[s] + adst;
        e = e > 0.f ? e : 0.2f * e;
        float al = expf(e - m) * rd;
        const float* hr = &g_H2[(size_t)s * OUT2];
        a0 = fmaf(al, hr[lane], a0);
        a1 = fmaf(al, hr[32 + lane], a1);
        a2 = fmaf(al, hr[64 + lane], a2);
        a3 = fmaf(al, hr[96 + lane], a3);
    }
    float v0 = fmaxf(a0 + b2[lane], 0.f);
    float v1 = fmaxf(a1 + b2[32 + lane], 0.f);
    float v2 = fmaxf(a2 + b2[64 + lane], 0.f);
    float v3 = fmaxf(a3 + b2[96 + lane], 0.f);
    float gp = v0 * wg[lane] + v1 * wg[32 + lane] + v2 * wg[64 + lane] + v3 * wg[96 + lane];
#pragma unroll
    for (int o = 16; o > 0; o >>= 1) gp += __shfl_xor_sync(0xffffffffu, gp, o);
    float w = 1.f / (1.f + expf(-(gp + bg[0])));
    int gr = batch[n];
    float* hs = &g_HSUM[(size_t)gr * OUT2];
    float* hm = &g_HMAX[(size_t)gr * OUT2];
    atomicAdd(&hs[lane], v0 * w);
    atomicAdd(&hs[32 + lane], v1 * w);
    atomicAdd(&hs[64 + lane], v2 * w);
    atomicAdd(&hs[96 + lane], v3 * w);
    atomicMax((int*)&hm[lane], __float_as_int(v0));
    atomicMax((int*)&hm[32 + lane], __float_as_int(v1));
    atomicMax((int*)&hm[64 + lane], __float_as_int(v2));
    atomicMax((int*)&hm[96 + lane], __float_as_int(v3));
}

// ---------------- tail ------------------------------------------------------
__global__ void k_concat() {
    int i = blockIdx.x * blockDim.x + threadIdx.x;
    if (i >= N_GRAPHS * 512) return;
    int g = i / 512, c = i - g * 512;
    float v;
    if (c < 128)      v = g_HSUM[g * 128 + c];
    else if (c < 256) v = g_HMAX[g * 128 + (c - 128)];
    else              v = g_XT[g * 256 + (c - 256)];
    g_XC[i] = v;
}
__global__ void k_out(const float* __restrict__ Wo, const float* __restrict__ bo,
                      float* __restrict__ out) {
    int g = blockIdx.x, lane = threadIdx.x;
    float s = 0.f;
    for (int k = lane; k < 256; k += 32) s += g_X2[g * 256 + k] * Wo[k];
#pragma unroll
    for (int o = 16; o > 0; o >>= 1) s += __shfl_down_sync(0xffffffffu, s, o);
    if (lane == 0) out[g] = s + bo[0];
}

// ---------------- host ------------------------------------------------------
static inline dim3 mma2_grid(int M, int N, int Z = 1) {
    return dim3((M + 63) / 64, (N + 127) / 128, Z);
}

extern "C" void kernel_launch(void* const* d_in, const int* in_sizes, int n_in,
                              void* d_out, int out_size) {
    const float* x      = (const float*)d_in[0];
    const int*   ei     = (const int*)d_in[1];
    const int*   batch  = (const int*)d_in[2];
    const float* target = (const float*)d_in[3];
    const float* W1  = (const float*)d_in[4];
    const float* as1 = (const float*)d_in[5];
    const float* ad1 = (const float*)d_in[6];
    const float* b1  = (const float*)d_in[7];
    const float* W2  = (const float*)d_in[8];
    const float* as2 = (const float*)d_in[9];
    const float* ad2 = (const float*)d_in[10];
    const float* b2  = (const float*)d_in[11];
    const float* wg  = (const float*)d_in[12];
    const float* bg  = (const float*)d_in[13];
    const float* Wxt = (const float*)d_in[14];
    const float* bxt = (const float*)d_in[15];
    const float* Wf1 = (const float*)d_in[16];
    const float* bf1 = (const float*)d_in[17];
    const float* Wf2 = (const float*)d_in[18];
    const float* bf2 = (const float*)d_in[19];
    const float* Wo  = (const float*)d_in[20];
    const float* bo  = (const float*)d_in[21];
    float* out = (float*)d_out;

    float *XAGG, *H1O, *H2, *W2AS, *W2AD, *AS2, *AD2, *XT, *XC, *X1, *X2;
    cudaGetSymbolAddress((void**)&XAGG, g_XAGG);
    cudaGetSymbolAddress((void**)&H1O, g_H1O);
    cudaGetSymbolAddress((void**)&H2,  g_H2);
    cudaGetSymbolAddress((void**)&W2AS, g_W2AS);
    cudaGetSymbolAddress((void**)&W2AD, g_W2AD);
    cudaGetSymbolAddress((void**)&AS2, g_AS2);
    cudaGetSymbolAddress((void**)&AD2, g_AD2);
    cudaGetSymbolAddress((void**)&XT,  g_XT);
    cudaGetSymbolAddress((void**)&XC,  g_XC);
    cudaGetSymbolAddress((void**)&X1,  g_X1);
    cudaGetSymbolAddress((void**)&X2,  g_X2);

    // CSR build + zero accumulators
    k_initdeg<<<(N_NODES + 255) / 256, 256>>>();
    k_hist<<<(N_EDGES + 255) / 256, 256>>>(ei);
    k_scan1<<<NB_SCAN, 1024>>>();
    k_scan2<<<1, 128>>>();
    k_scan3<<<(N_NODES + 255) / 256, 256>>>();
    k_scatter<<<(E_TOT + 255) / 256, 256>>>(ei);
    k_zero<<<(N_GRAPHS * OUT2 + 255) / 256, 256>>>();

    // weight prep
    k_prep_att<<<(F_IN * 2 * H1N + 255) / 256, 256>>>(W1, as1, ad1);
    k_prep2v<<<(C1 + 255) / 256, 256>>>(W2, as2, ad2);

    // layer 1: logits -> fused softmax+agg (warp/node) -> batched GEMM (+att2 fold)
    k_att1<<<(N_NODES + 7) / 8, 256>>>(x);
    k_aggx_w<<<(N_NODES + 7) / 8, 256>>>(x);
    k_mma2<<<mma2_grid(N_NODES, F_IN, H1N), 256>>>(
        XAGG, W1, b1, H1O, N_NODES, F_IN, F_IN, C1, C1, C1, 2,
        F_IN, F_IN, F_IN, F_IN,
        W2AS, W2AD, F_IN, AS2, AD2);

    // layer 2: H2 = H1O @ W2  [100000,780]x[780,128] — exact single column tile
    k_mma2<<<mma2_grid(N_NODES, OUT2), 256>>>(H1O, W2, nullptr, H2,
                                              N_NODES, C1, OUT2, C1, OUT2, OUT2, 0,
                                              0, 0, 0, 0, nullptr, nullptr, 0, nullptr, nullptr);
    k_agg2_w<<<(N_NODES + 7) / 8, 256>>>(b2, wg, bg, batch);

    // tail MLP
    k_mma2<<<mma2_grid(N_GRAPHS, 256), 256>>>(target, Wxt, bxt, XT,
                                              N_GRAPHS, 1280, 256, 1280, 256, 256, 0,
                                              0, 0, 0, 0, nullptr, nullptr, 0, nullptr, nullptr);
    k_concat<<<(N_GRAPHS * 512 + 255) / 256, 256>>>();
    k_mma2<<<mma2_grid(N_GRAPHS, 1024), 256>>>(XC, Wf1, bf1, X1,
                                               N_GRAPHS, 512, 1024, 512, 1024, 1024, 1,
                                               0, 0, 0, 0, nullptr, nullptr, 0, nullptr, nullptr);
    k_mma2<<<mma2_grid(N_GRAPHS, 256), 256>>>(X1, Wf2, bf2, X2,
                                              N_GRAPHS, 1024, 256, 1024, 256, 256, 1,
                                              0, 0, 0, 0, nullptr, nullptr, 0, nullptr, nullptr);
    k_out<<<N_GRAPHS, 32>>>(Wo, bo, out);
}

// round 6
// speedup vs baseline: 3.0056x; 1.4518x over previous
#include <cuda_runtime.h>
#include <math.h>
#include <stdint.h>

#define N_NODES 100000
#define N_EDGES 400000
#define E_TOT   500000
#define N_GRAPHS 2048
#define F_IN 78
#define H1N 10
#define C1  780      // 10*78
#define C1P 800      // padded: 10 heads * 80
#define OUT2 128
#define NB_SCAN 98   // ceil(100000/1024)

// ---------------- scratch (device globals; no allocation allowed) -----------
__device__ __align__(16) float g_XAGG[N_NODES * C1P + 32 * C1P]; // padded pitch-80/head
__device__ __align__(16) float g_H1O[N_NODES * C1 + 32 * C1];
__device__ __align__(16) float g_H2[N_NODES * OUT2];
__device__ float g_ASD1[N_NODES * 2 * H1N];
__device__ float g_AS2[N_NODES], g_AD2[N_NODES];
__device__ int   g_DEG[N_NODES], g_INCL[N_NODES], g_BSUM[128], g_BOFF[128];
__device__ int   g_OFF[N_NODES + 1], g_CUR[N_NODES], g_CSRC[E_TOT];
__device__ float g_WATT[F_IN * 2 * H1N];
__device__ __align__(16) float g_W1P[F_IN * C1P];   // W1 re-laid to pitch 80/head
__device__ float g_W2AS[C1], g_W2AD[C1];
__device__ float g_HSUM[N_GRAPHS * OUT2], g_HMAX[N_GRAPHS * OUT2];
__device__ __align__(16) float g_XT[N_GRAPHS * 256];
__device__ __align__(16) float g_XC[N_GRAPHS * 512];
__device__ __align__(16) float g_X1[N_GRAPHS * 1024];
__device__ __align__(16) float g_X2[N_GRAPHS * 256];

// ---------------- CSR build -----------------------------------------------
__global__ void k_initdeg() {
    int i = blockIdx.x * blockDim.x + threadIdx.x;
    if (i < N_NODES) g_DEG[i] = 1;
}
__global__ void k_hist(const int* __restrict__ ei) {
    int e = blockIdx.x * blockDim.x + threadIdx.x;
    if (e < N_EDGES) atomicAdd(&g_DEG[ei[N_EDGES + e]], 1);
}
__global__ void k_scan1() {
    __shared__ int sw[32];
    int i = blockIdx.x * 1024 + threadIdx.x;
    int v = (i < N_NODES) ? g_DEG[i] : 0;
    int lane = threadIdx.x & 31, w = threadIdx.x >> 5;
    int x = v;
#pragma unroll
    for (int o = 1; o < 32; o <<= 1) {
        int y = __shfl_up_sync(0xffffffffu, x, o);
        if (lane >= o) x += y;
    }
    if (lane == 31) sw[w] = x;
    __syncthreads();
    if (w == 0) {
        int s = sw[lane];
#pragma unroll
        for (int o = 1; o < 32; o <<= 1) {
            int y = __shfl_up_sync(0xffffffffu, s, o);
            if (lane >= o) s += y;
        }
        sw[lane] = s;
    }
    __syncthreads();
    if (w > 0) x += sw[w - 1];
    if (i < N_NODES) g_INCL[i] = x;
    if (threadIdx.x == 1023) g_BSUM[blockIdx.x] = x;
}
__global__ void k_scan2() {
    __shared__ int sw[4];
    int t = threadIdx.x;
    int v = (t < NB_SCAN) ? g_BSUM[t] : 0;
    int lane = t & 31, w = t >> 5;
    int x = v;
#pragma unroll
    for (int o = 1; o < 32; o <<= 1) {
        int y = __shfl_up_sync(0xffffffffu, x, o);
        if (lane >= o) x += y;
    }
    if (lane == 31) sw[w] = x;
    __syncthreads();
    int add = 0;
    for (int i = 0; i < w; i++) add += sw[i];
    x += add;
    if (t < NB_SCAN) g_BOFF[t] = x - v;
}
__global__ void k_scan3() {
    int i = blockIdx.x * blockDim.x + threadIdx.x;
    if (i < N_NODES) {
        int off = g_INCL[i] - g_DEG[i] + g_BOFF[i >> 10];
        g_OFF[i] = off;
        g_CUR[i] = off;
        if (i == 0) g_OFF[N_NODES] = E_TOT;
    }
}
__global__ void k_scatter(const int* __restrict__ ei) {
    int i = blockIdx.x * blockDim.x + threadIdx.x;
    if (i >= E_TOT) return;
    int s, d;
    if (i < N_EDGES) { s = ei[i]; d = ei[N_EDGES + i]; }
    else             { s = d = i - N_EDGES; }
    int pos = atomicAdd(&g_CUR[d], 1);
    g_CSRC[pos] = s;
}

// ---------------- zero-init ----------------------------------------------
__global__ void k_zero() {
    int i = blockIdx.x * blockDim.x + threadIdx.x;
    if (i < N_GRAPHS * OUT2) { g_HSUM[i] = 0.f; g_HMAX[i] = 0.f; }
    if (i < N_NODES) { g_AS2[i] = 0.f; g_AD2[i] = 0.f; }
}

// ---------------- weight prep ----------------------------------------------
__global__ void k_prep_att(const float* __restrict__ W1, const float* __restrict__ as,
                           const float* __restrict__ ad) {
    int i = blockIdx.x * blockDim.x + threadIdx.x;
    if (i >= F_IN * 2 * H1N) return;
    int k = i / (2 * H1N), j = i - k * (2 * H1N);
    const float* a = (j < H1N) ? (as + j * F_IN) : (ad + (j - H1N) * F_IN);
    int h = (j < H1N) ? j : j - H1N;
    float s = 0.f;
    for (int d = 0; d < F_IN; d++) s += W1[k * C1 + h * F_IN + d] * a[d];
    g_WATT[i] = s;
}
__global__ void k_prep_w1p(const float* __restrict__ W1) {
    int i = blockIdx.x * blockDim.x + threadIdx.x;
    if (i >= F_IN * C1) return;
    int k = i / C1, c = i - k * C1;
    int h = c / F_IN, d = c - h * F_IN;
    g_W1P[k * C1P + h * 80 + d] = W1[i];
}
__global__ void k_prep2v(const float* __restrict__ W2, const float* __restrict__ as,
                         const float* __restrict__ ad) {
    int k = blockIdx.x * blockDim.x + threadIdx.x;
    if (k >= C1) return;
    float s = 0.f, t = 0.f;
    for (int d = 0; d < OUT2; d++) {
        float w = W2[k * OUT2 + d];
        s = fmaf(w, as[d], s);
        t = fmaf(w, ad[d], t);
    }
    g_W2AS[k] = s;
    g_W2AD[k] = t;
}

// ---------------- attention logits ------------------------------------------
__global__ void k_att1(const float* __restrict__ x) {
    __shared__ float sW[F_IN * 2 * H1N];
    __shared__ float sX[8 * F_IN];
    int tid = threadIdx.x, w = tid >> 5, lane = tid & 31;
    for (int i = tid; i < F_IN * 2 * H1N; i += 256) sW[i] = g_WATT[i];
    int n = blockIdx.x * 8 + w;
    if (n < N_NODES) {
        for (int d = lane; d < F_IN; d += 32) sX[w * F_IN + d] = x[(size_t)n * F_IN + d];
    }
    __syncthreads();
    if (n >= N_NODES || lane >= 2 * H1N) return;
    float s = 0.f;
    for (int d = 0; d < F_IN; d++)
        s = fmaf(sX[w * F_IN + d], sW[d * 2 * H1N + lane], s);
    g_ASD1[n * 2 * H1N + lane] = s;
}

// ---------------- layer 1: fused softmax + x-space aggregation (warp/node) --
__global__ void k_aggx_w(const float* __restrict__ x) {
    int n = blockIdx.x * 8 + (threadIdx.x >> 5);
    if (n >= N_NODES) return;
    int lane = threadIdx.x & 31;
    int p0 = g_OFF[n], p1 = g_OFF[n + 1];
    float adst = (lane < H1N) ? g_ASD1[n * 2 * H1N + H1N + lane] : 0.f;
    float m = -1e30f;
    for (int p = p0; p < p1; p++) {
        int s = g_CSRC[p];
        if (lane < H1N) {
            float e = g_ASD1[s * 2 * H1N + lane] + adst;
            e = e > 0.f ? e : 0.2f * e;
            m = fmaxf(m, e);
        }
    }
    float den = 0.f;
    for (int p = p0; p < p1; p++) {
        int s = g_CSRC[p];
        if (lane < H1N) {
            float e = g_ASD1[s * 2 * H1N + lane] + adst;
            e = e > 0.f ? e : 0.2f * e;
            den += expf(e - m);
        }
    }
    float rd = 1.f / (den + 1e-16f);
    float acc[H1N][3];
#pragma unroll
    for (int h = 0; h < H1N; h++) { acc[h][0] = 0.f; acc[h][1] = 0.f; acc[h][2] = 0.f; }
    for (int p = p0; p < p1; p++) {
        int s = g_CSRC[p];
        float al = 0.f;
        if (lane < H1N) {
            float e = g_ASD1[s * 2 * H1N + lane] + adst;
            e = e > 0.f ? e : 0.2f * e;
            al = expf(e - m) * rd;
        }
        const float* xr = &x[(size_t)s * F_IN];
        float xv0 = xr[lane];
        float xv1 = xr[32 + lane];
        float xv2 = (lane < F_IN - 64) ? xr[64 + lane] : 0.f;
#pragma unroll
        for (int h = 0; h < H1N; h++) {
            float a = __shfl_sync(0xffffffffu, al, h);
            acc[h][0] = fmaf(a, xv0, acc[h][0]);
            acc[h][1] = fmaf(a, xv1, acc[h][1]);
            acc[h][2] = fmaf(a, xv2, acc[h][2]);
        }
    }
    size_t base = (size_t)n * C1P;
#pragma unroll
    for (int h = 0; h < H1N; h++) {
        g_XAGG[base + h * 80 + lane] = acc[h][0];
        g_XAGG[base + h * 80 + 32 + lane] = acc[h][1];
        if (lane < F_IN - 64) g_XAGG[base + h * 80 + 64 + lane] = acc[h][2];
    }
}

// ---------------- TF32 GEMM: 64x128 tile, 8 warps, cp.async double-buffered --
#define PAp 20
#define PBp 136

__device__ __forceinline__ uint32_t f2tf32(float v) {
    uint32_t u;
    asm("cvt.rna.tf32.f32 %0, %1;" : "=r"(u) : "f"(v));
    return u;
}
__device__ __forceinline__ void cp16(uint32_t dst, const float* src, int nbytes) {
    asm volatile("cp.async.cg.shared.global [%0], [%1], 16, %2;\n"
                 :: "r"(dst), "l"(src), "r"(nbytes));
}

// act: 0 none, 1 relu, 2 elu. A rows may read past M (oversized/aligned buffers);
// B is zero-filled past K rows and N cols. C stores guarded.
__global__ void __launch_bounds__(256) k_mma3(
    const float* __restrict__ A_, const float* __restrict__ B_,
    const float* __restrict__ bias_, float* __restrict__ C_,
    int M, int K, int N, int lda, int ldb, int ldC, int act,
    long long stA, long long stB, long long stBias, long long stC,
    const float* __restrict__ attS_, const float* __restrict__ attD_,
    long long stAtt, float* __restrict__ outAS, float* __restrict__ outAD) {
    __shared__ __align__(16) float sA[2][64 * PAp];
    __shared__ __align__(16) float sB[2][16 * PBp];
    const float* A = A_ + (long long)blockIdx.z * stA;
    const float* B = B_ + (long long)blockIdx.z * stB;
    const float* bias = bias_ ? bias_ + (long long)blockIdx.z * stBias : nullptr;
    float* C = C_ + (long long)blockIdx.z * stC;
    const float* attS = attS_ ? attS_ + (long long)blockIdx.z * stAtt : nullptr;
    const float* attD = attD_ ? attD_ + (long long)blockIdx.z * stAtt : nullptr;

    int t = threadIdx.x;
    int warp = t >> 5, lane = t & 31;
    int g = lane >> 2, tg = lane & 3;
    int wm = warp >> 2, wn = warp & 3;
    int r0 = blockIdx.x * 64;
    int c0 = blockIdx.y * 128;

    // cp.async source indices
    int arow = t >> 2, acol = (t & 3) * 4;                  // 1 float4 for A
    const float* aptr = A + (size_t)(r0 + arow) * lda + acol;
    uint32_t sa_dst[2], sb_dst[2][2];
    sa_dst[0] = (uint32_t)__cvta_generic_to_shared(&sA[0][arow * PAp + acol]);
    sa_dst[1] = (uint32_t)__cvta_generic_to_shared(&sA[1][arow * PAp + acol]);
    int brow[2], bcol[2];
#pragma unroll
    for (int i = 0; i < 2; i++) {
        int id = t + i * 256;
        brow[i] = id >> 5;
        bcol[i] = (id & 31) * 4;
        sb_dst[0][i] = (uint32_t)__cvta_generic_to_shared(&sB[0][brow[i] * PBp + bcol[i]]);
        sb_dst[1][i] = (uint32_t)__cvta_generic_to_shared(&sB[1][brow[i] * PBp + bcol[i]]);
    }

    int niter = (K + 15) / 16;
    // prologue: stage 0
    {
        cp16(sa_dst[0], aptr, 16);
#pragma unroll
        for (int i = 0; i < 2; i++) {
            const float* src = B + (size_t)brow[i] * ldb + c0 + bcol[i];
            int nb = 0;
            if (brow[i] < K) {
                int v = N - (c0 + bcol[i]);
                nb = v >= 4 ? 16 : (v > 0 ? v * 4 : 0);
            }
            if (nb == 0) src = B;
            cp16(sb_dst[0][i], src, nb);
        }
        asm volatile("cp.async.commit_group;\n");
    }

    float acc[2][4][4];
#pragma unroll
    for (int mi = 0; mi < 2; mi++)
#pragma unroll
        for (int ni = 0; ni < 4; ni++)
#pragma unroll
            for (int r = 0; r < 4; r++) acc[mi][ni][r] = 0.f;

    for (int it = 0; it < niter; it++) {
        if (it + 1 < niter) {
            int kt = (it + 1) * 16;
            int buf = (it + 1) & 1;
            cp16(sa_dst[buf], aptr + kt, 16);
#pragma unroll
            for (int i = 0; i < 2; i++) {
                const float* src = B + (size_t)(kt + brow[i]) * ldb + c0 + bcol[i];
                int nb = 0;
                if (kt + brow[i] < K) {
                    int v = N - (c0 + bcol[i]);
                    nb = v >= 4 ? 16 : (v > 0 ? v * 4 : 0);
                }
                if (nb == 0) src = B;
                cp16(sb_dst[buf][i], src, nb);
            }
            asm volatile("cp.async.commit_group;\n");
            asm volatile("cp.async.wait_group 1;\n");
        } else {
            asm volatile("cp.async.wait_group 0;\n");
        }
        __syncthreads();
        int cb = it & 1;
#pragma unroll
        for (int kk = 0; kk < 16; kk += 8) {
            uint32_t af[2][4];
#pragma unroll
            for (int mi = 0; mi < 2; mi++) {
                int br = wm * 32 + mi * 16;
                af[mi][0] = f2tf32(sA[cb][(br + g) * PAp + kk + tg]);
                af[mi][1] = f2tf32(sA[cb][(br + g + 8) * PAp + kk + tg]);
                af[mi][2] = f2tf32(sA[cb][(br + g) * PAp + kk + tg + 4]);
                af[mi][3] = f2tf32(sA[cb][(br + g + 8) * PAp + kk + tg + 4]);
            }
            uint32_t bf[4][2];
#pragma unroll
            for (int ni = 0; ni < 4; ni++) {
                int bc = wn * 32 + ni * 8 + g;
                bf[ni][0] = f2tf32(sB[cb][(kk + tg) * PBp + bc]);
                bf[ni][1] = f2tf32(sB[cb][(kk + tg + 4) * PBp + bc]);
            }
#pragma unroll
            for (int mi = 0; mi < 2; mi++)
#pragma unroll
                for (int ni = 0; ni < 4; ni++) {
                    asm volatile(
                        "mma.sync.aligned.m16n8k8.row.col.f32.tf32.tf32.f32 "
                        "{%0,%1,%2,%3}, {%4,%5,%6,%7}, {%8,%9}, {%0,%1,%2,%3};\n"
                        : "+f"(acc[mi][ni][0]), "+f"(acc[mi][ni][1]),
                          "+f"(acc[mi][ni][2]), "+f"(acc[mi][ni][3])
                        : "r"(af[mi][0]), "r"(af[mi][1]), "r"(af[mi][2]), "r"(af[mi][3]),
                          "r"(bf[ni][0]), "r"(bf[ni][1]));
                }
        }
        __syncthreads();
    }
    // epilogue
#pragma unroll
    for (int mi = 0; mi < 2; mi++) {
#pragma unroll
        for (int half = 0; half < 2; half++) {
            int row = r0 + wm * 32 + mi * 16 + g + half * 8;
            float ps = 0.f, pd = 0.f;
#pragma unroll
            for (int ni = 0; ni < 4; ni++) {
                int col = c0 + wn * 32 + ni * 8 + tg * 2;
#pragma unroll
                for (int q = 0; q < 2; q++) {
                    if (row < M && col + q < N) {
                        float v = acc[mi][ni][half * 2 + q] + (bias ? bias[col + q] : 0.f);
                        if (act == 1) v = fmaxf(v, 0.f);
                        else if (act == 2) v = v > 0.f ? v : expm1f(v);
                        C[(size_t)row * ldC + col + q] = v;
                        if (attS) {
                            ps = fmaf(v, attS[col + q], ps);
                            pd = fmaf(v, attD[col + q], pd);
                        }
                    }
                }
            }
            if (attS) {
                ps += __shfl_xor_sync(0xffffffffu, ps, 1);
                ps += __shfl_xor_sync(0xffffffffu, ps, 2);
                pd += __shfl_xor_sync(0xffffffffu, pd, 1);
                pd += __shfl_xor_sync(0xffffffffu, pd, 2);
                if (tg == 0 && row < M) {
                    atomicAdd(&outAS[row], ps);
                    atomicAdd(&outAD[row], pd);
                }
            }
        }
    }
}

// ---------------- layer 2: fused softmax + aggregation + readout ------------
__global__ void k_agg2_w(const float* __restrict__ b2, const float* __restrict__ wg,
                         const float* __restrict__ bg, const int* __restrict__ batch) {
    int n = blockIdx.x * 8 + (threadIdx.x >> 5);
    if (n >= N_NODES) return;
    int lane = threadIdx.x & 31;
    int p0 = g_OFF[n], p1 = g_OFF[n + 1];
    float adst = g_AD2[n];
    float m = -1e30f;
    for (int p = p0; p < p1; p++) {
        float e = g_AS2[g_CSRC[p]] + adst;
        e = e > 0.f ? e : 0.2f * e;
        m = fmaxf(m, e);
    }
    float den = 0.f;
    for (int p = p0; p < p1; p++) {
        float e = g_AS2[g_CSRC[p]] + adst;
        e = e > 0.f ? e : 0.2f * e;
        den += expf(e - m);
    }
    float rd = 1.f / (den + 1e-16f);
    float a0 = 0.f, a1 = 0.f, a2 = 0.f, a3 = 0.f;
    for (int p = p0; p < p1; p++) {
        int s = g_CSRC[p];
        float e = g_AS2[s] + adst;
        e = e > 0.f ? e : 0.2f * e;
        float al = expf(e - m) * rd;
        const float* hr = &g_H2[(size_t)s * OUT2];
        a0 = fmaf(al, hr[lane], a0);
        a1 = fmaf(al, hr[32 + lane], a1);
        a2 = fmaf(al, hr[64 + lane], a2);
        a3 = fmaf(al, hr[96 + lane], a3);
    }
    float v0 = fmaxf(a0 + b2[lane], 0.f);
    float v1 = fmaxf(a1 + b2[32 + lane], 0.f);
    float v2 = fmaxf(a2 + b2[64 + lane], 0.f);
    float v3 = fmaxf(a3 + b2[96 + lane], 0.f);
    float gp = v0 * wg[lane] + v1 * wg[32 + lane] + v2 * wg[64 + lane] + v3 * wg[96 + lane];
#pragma unroll
    for (int o = 16; o > 0; o >>= 1) gp += __shfl_xor_sync(0xffffffffu, gp, o);
    float w = 1.f / (1.f + expf(-(gp + bg[0])));
    int gr = batch[n];
    float* hs = &g_HSUM[(size_t)gr * OUT2];
    float* hm = &g_HMAX[(size_t)gr * OUT2];
    atomicAdd(&hs[lane], v0 * w);
    atomicAdd(&hs[32 + lane], v1 * w);
    atomicAdd(&hs[64 + lane], v2 * w);
    atomicAdd(&hs[96 + lane], v3 * w);
    atomicMax((int*)&hm[lane], __float_as_int(v0));
    atomicMax((int*)&hm[32 + lane], __float_as_int(v1));
    atomicMax((int*)&hm[64 + lane], __float_as_int(v2));
    atomicMax((int*)&hm[96 + lane], __float_as_int(v3));
}

// ---------------- tail ------------------------------------------------------
__global__ void k_concat() {
    int i = blockIdx.x * blockDim.x + threadIdx.x;
    if (i >= N_GRAPHS * 512) return;
    int g = i / 512, c = i - g * 512;
    float v;
    if (c < 128)      v = g_HSUM[g * 128 + c];
    else if (c < 256) v = g_HMAX[g * 128 + (c - 128)];
    else              v = g_XT[g * 256 + (c - 256)];
    g_XC[i] = v;
}
__global__ void k_out(const float* __restrict__ Wo, const float* __restrict__ bo,
                      float* __restrict__ out) {
    int g = blockIdx.x, lane = threadIdx.x;
    float s = 0.f;
    for (int k = lane; k < 256; k += 32) s += g_X2[g * 256 + k] * Wo[k];
#pragma unroll
    for (int o = 16; o > 0; o >>= 1) s += __shfl_down_sync(0xffffffffu, s, o);
    if (lane == 0) out[g] = s + bo[0];
}

// ---------------- host ------------------------------------------------------
static inline dim3 mma_grid(int M, int N, int Z = 1) {
    return dim3((M + 63) / 64, (N + 127) / 128, Z);
}

extern "C" void kernel_launch(void* const* d_in, const int* in_sizes, int n_in,
                              void* d_out, int out_size) {
    const float* x      = (const float*)d_in[0];
    const int*   ei     = (const int*)d_in[1];
    const int*   batch  = (const int*)d_in[2];
    const float* target = (const float*)d_in[3];
    const float* W1  = (const float*)d_in[4];
    const float* as1 = (const float*)d_in[5];
    const float* ad1 = (const float*)d_in[6];
    const float* b1  = (const float*)d_in[7];
    const float* W2  = (const float*)d_in[8];
    const float* as2 = (const float*)d_in[9];
    const float* ad2 = (const float*)d_in[10];
    const float* b2  = (const float*)d_in[11];
    const float* wg  = (const float*)d_in[12];
    const float* bg  = (const float*)d_in[13];
    const float* Wxt = (const float*)d_in[14];
    const float* bxt = (const float*)d_in[15];
    const float* Wf1 = (const float*)d_in[16];
    const float* bf1 = (const float*)d_in[17];
    const float* Wf2 = (const float*)d_in[18];
    const float* bf2 = (const float*)d_in[19];
    const float* Wo  = (const float*)d_in[20];
    const float* bo  = (const float*)d_in[21];
    float* out = (float*)d_out;

    float *XAGG, *H1O, *H2, *W1P, *W2AS, *W2AD, *AS2, *AD2, *XT, *XC, *X1, *X2;
    cudaGetSymbolAddress((void**)&XAGG, g_XAGG);
    cudaGetSymbolAddress((void**)&H1O, g_H1O);
    cudaGetSymbolAddress((void**)&H2,  g_H2);
    cudaGetSymbolAddress((void**)&W1P, g_W1P);
    cudaGetSymbolAddress((void**)&W2AS, g_W2AS);
    cudaGetSymbolAddress((void**)&W2AD, g_W2AD);
    cudaGetSymbolAddress((void**)&AS2, g_AS2);
    cudaGetSymbolAddress((void**)&AD2, g_AD2);
    cudaGetSymbolAddress((void**)&XT,  g_XT);
    cudaGetSymbolAddress((void**)&XC,  g_XC);
    cudaGetSymbolAddress((void**)&X1,  g_X1);
    cudaGetSymbolAddress((void**)&X2,  g_X2);

    // CSR build + zero accumulators
    k_initdeg<<<(N_NODES + 255) / 256, 256>>>();
    k_hist<<<(N_EDGES + 255) / 256, 256>>>(ei);
    k_scan1<<<NB_SCAN, 1024>>>();
    k_scan2<<<1, 128>>>();
    k_scan3<<<(N_NODES + 255) / 256, 256>>>();
    k_scatter<<<(E_TOT + 255) / 256, 256>>>(ei);
    k_zero<<<(N_GRAPHS * OUT2 + 255) / 256, 256>>>();

    // weight prep
    k_prep_att<<<(F_IN * 2 * H1N + 255) / 256, 256>>>(W1, as1, ad1);
    k_prep_w1p<<<(F_IN * C1 + 255) / 256, 256>>>(W1);
    k_prep2v<<<(C1 + 255) / 256, 256>>>(W2, as2, ad2);

    // layer 1: logits -> fused softmax+agg -> batched GEMM (+att2 fold)
    k_att1<<<(N_NODES + 7) / 8, 256>>>(x);
    k_aggx_w<<<(N_NODES + 7) / 8, 256>>>(x);
    k_mma3<<<mma_grid(N_NODES, F_IN, H1N), 256>>>(
        XAGG, W1P, b1, H1O, N_NODES, F_IN, F_IN, C1P, C1P, C1, 2,
        80, 80, F_IN, F_IN,
        W2AS, W2AD, F_IN, AS2, AD2);

    // layer 2: H2 = H1O @ W2  [100000,780]x[780,128]
    k_mma3<<<mma_grid(N_NODES, OUT2), 256>>>(H1O, W2, nullptr, H2,
                                             N_NODES, C1, OUT2, C1, OUT2, OUT2, 0,
                                             0, 0, 0, 0, nullptr, nullptr, 0, nullptr, nullptr);
    k_agg2_w<<<(N_NODES + 7) / 8, 256>>>(b2, wg, bg, batch);

    // tail MLP
    k_mma3<<<mma_grid(N_GRAPHS, 256), 256>>>(target, Wxt, bxt, XT,
                                             N_GRAPHS, 1280, 256, 1280, 256, 256, 0,
                                             0, 0, 0, 0, nullptr, nullptr, 0, nullptr, nullptr);
    k_concat<<<(N_GRAPHS * 512 + 255) / 256, 256>>>();
    k_mma3<<<mma_grid(N_GRAPHS, 1024), 256>>>(XC, Wf1, bf1, X1,
                                              N_GRAPHS, 512, 1024, 512, 1024, 1024, 1,
                                              0, 0, 0, 0, nullptr, nullptr, 0, nullptr, nullptr);
    k_mma3<<<mma_grid(N_GRAPHS, 256), 256>>>(X1, Wf2, bf2, X2,
                                             N_GRAPHS, 1024, 256, 1024, 256, 256, 1,
                                             0, 0, 0, 0, nullptr, nullptr, 0, nullptr, nullptr);
    k_out<<<N_GRAPHS, 32>>>(Wo, bo, out);
}

// round 7
// speedup vs baseline: 3.0269x; 1.0071x over previous
#include <cuda_runtime.h>
#include <math.h>
#include <stdint.h>

#define N_NODES 100000
#define N_EDGES 400000
#define E_TOT   500000
#define N_GRAPHS 2048
#define F_IN 78
#define H1N 10
#define C1  780      // 10*78
#define C1P 800      // padded: 10 heads * 80
#define OUT2 128
#define NB_SCAN 98   // ceil(100000/1024)

// ---------------- scratch (device globals; no allocation allowed) -----------
__device__ __align__(16) float g_XAGG[N_NODES * C1P + 32 * C1P]; // padded pitch-80/head
__device__ __align__(16) float g_H1O[N_NODES * C1 + 32 * C1];
__device__ __align__(16) float g_H2[N_NODES * OUT2];
__device__ float g_ASD1[N_NODES * 2 * H1N];
__device__ float g_AS2[N_NODES], g_AD2[N_NODES];
__device__ int   g_DEG[N_NODES], g_INCL[N_NODES], g_BSUM[128], g_BOFF[128];
__device__ int   g_OFF[N_NODES + 1], g_CUR[N_NODES], g_CSRC[E_TOT];
__device__ float g_WATT[F_IN * 2 * H1N];
__device__ __align__(16) float g_W1P[F_IN * C1P];   // W1 re-laid to pitch 80/head
__device__ float g_W2AS[C1], g_W2AD[C1];
__device__ float g_HSUM[N_GRAPHS * OUT2], g_HMAX[N_GRAPHS * OUT2];
__device__ __align__(16) float g_XT[N_GRAPHS * 256];
__device__ __align__(16) float g_XC[N_GRAPHS * 512];
__device__ __align__(16) float g_X1[N_GRAPHS * 1024];
__device__ __align__(16) float g_X2[N_GRAPHS * 256];

// ---------------- CSR build -----------------------------------------------
__global__ void k_initdeg() {
    int i = blockIdx.x * blockDim.x + threadIdx.x;
    if (i < N_NODES) g_DEG[i] = 1;
}
__global__ void k_hist(const int* __restrict__ ei) {
    int e = blockIdx.x * blockDim.x + threadIdx.x;
    if (e < N_EDGES) atomicAdd(&g_DEG[ei[N_EDGES + e]], 1);
}
__global__ void k_scan1() {
    __shared__ int sw[32];
    int i = blockIdx.x * 1024 + threadIdx.x;
    int v = (i < N_NODES) ? g_DEG[i] : 0;
    int lane = threadIdx.x & 31, w = threadIdx.x >> 5;
    int x = v;
#pragma unroll
    for (int o = 1; o < 32; o <<= 1) {
        int y = __shfl_up_sync(0xffffffffu, x, o);
        if (lane >= o) x += y;
    }
    if (lane == 31) sw[w] = x;
    __syncthreads();
    if (w == 0) {
        int s = sw[lane];
#pragma unroll
        for (int o = 1; o < 32; o <<= 1) {
            int y = __shfl_up_sync(0xffffffffu, s, o);
            if (lane >= o) s += y;
        }
        sw[lane] = s;
    }
    __syncthreads();
    if (w > 0) x += sw[w - 1];
    if (i < N_NODES) g_INCL[i] = x;
    if (threadIdx.x == 1023) g_BSUM[blockIdx.x] = x;
}
__global__ void k_scan2() {
    __shared__ int sw[4];
    int t = threadIdx.x;
    int v = (t < NB_SCAN) ? g_BSUM[t] : 0;
    int lane = t & 31, w = t >> 5;
    int x = v;
#pragma unroll
    for (int o = 1; o < 32; o <<= 1) {
        int y = __shfl_up_sync(0xffffffffu, x, o);
        if (lane >= o) x += y;
    }
    if (lane == 31) sw[w] = x;
    __syncthreads();
    int add = 0;
    for (int i = 0; i < w; i++) add += sw[i];
    x += add;
    if (t < NB_SCAN) g_BOFF[t] = x - v;
}
__global__ void k_scan3() {
    int i = blockIdx.x * blockDim.x + threadIdx.x;
    if (i < N_NODES) {
        int off = g_INCL[i] - g_DEG[i] + g_BOFF[i >> 10];
        g_OFF[i] = off;
        g_CUR[i] = off;
        if (i == 0) g_OFF[N_NODES] = E_TOT;
    }
}
__global__ void k_scatter(const int* __restrict__ ei) {
    int i = blockIdx.x * blockDim.x + threadIdx.x;
    if (i >= E_TOT) return;
    int s, d;
    if (i < N_EDGES) { s = ei[i]; d = ei[N_EDGES + i]; }
    else             { s = d = i - N_EDGES; }
    int pos = atomicAdd(&g_CUR[d], 1);
    g_CSRC[pos] = s;
}

// ---------------- zero-init ----------------------------------------------
__global__ void k_zero() {
    int i = blockIdx.x * blockDim.x + threadIdx.x;
    if (i < N_GRAPHS * OUT2) { g_HSUM[i] = 0.f; g_HMAX[i] = 0.f; }
    if (i < N_NODES) { g_AS2[i] = 0.f; g_AD2[i] = 0.f; }
}

// ---------------- weight prep ----------------------------------------------
__global__ void k_prep_att(const float* __restrict__ W1, const float* __restrict__ as,
                           const float* __restrict__ ad) {
    int i = blockIdx.x * blockDim.x + threadIdx.x;
    if (i >= F_IN * 2 * H1N) return;
    int k = i / (2 * H1N), j = i - k * (2 * H1N);
    const float* a = (j < H1N) ? (as + j * F_IN) : (ad + (j - H1N) * F_IN);
    int h = (j < H1N) ? j : j - H1N;
    float s = 0.f;
    for (int d = 0; d < F_IN; d++) s += W1[k * C1 + h * F_IN + d] * a[d];
    g_WATT[i] = s;
}
__global__ void k_prep_w1p(const float* __restrict__ W1) {
    int i = blockIdx.x * blockDim.x + threadIdx.x;
    if (i >= F_IN * C1) return;
    int k = i / C1, c = i - k * C1;
    int h = c / F_IN, d = c - h * F_IN;
    g_W1P[k * C1P + h * 80 + d] = W1[i];
}
__global__ void k_prep2v(const float* __restrict__ W2, const float* __restrict__ as,
                         const float* __restrict__ ad) {
    int k = blockIdx.x * blockDim.x + threadIdx.x;
    if (k >= C1) return;
    float s = 0.f, t = 0.f;
    for (int d = 0; d < OUT2; d++) {
        float w = W2[k * OUT2 + d];
        s = fmaf(w, as[d], s);
        t = fmaf(w, ad[d], t);
    }
    g_W2AS[k] = s;
    g_W2AD[k] = t;
}

// ---------------- attention logits ------------------------------------------
__global__ void k_att1(const float* __restrict__ x) {
    __shared__ float sW[F_IN * 2 * H1N];
    __shared__ float sX[8 * F_IN];
    int tid = threadIdx.x, w = tid >> 5, lane = tid & 31;
    for (int i = tid; i < F_IN * 2 * H1N; i += 256) sW[i] = g_WATT[i];
    int n = blockIdx.x * 8 + w;
    if (n < N_NODES) {
        for (int d = lane; d < F_IN; d += 32) sX[w * F_IN + d] = x[(size_t)n * F_IN + d];
    }
    __syncthreads();
    if (n >= N_NODES || lane >= 2 * H1N) return;
    float s = 0.f;
    for (int d = 0; d < F_IN; d++)
        s = fmaf(sX[w * F_IN + d], sW[d * 2 * H1N + lane], s);
    g_ASD1[n * 2 * H1N + lane] = s;
}

// ---------------- layer 1: fused softmax + x-space aggregation (warp/node) --
__global__ void k_aggx_w(const float* __restrict__ x) {
    int n = blockIdx.x * 8 + (threadIdx.x >> 5);
    if (n >= N_NODES) return;
    int lane = threadIdx.x & 31;
    int p0 = g_OFF[n], p1 = g_OFF[n + 1];
    float adst = (lane < H1N) ? g_ASD1[n * 2 * H1N + H1N + lane] : 0.f;
    float m = -1e30f;
    for (int p = p0; p < p1; p++) {
        int s = g_CSRC[p];
        if (lane < H1N) {
            float e = g_ASD1[s * 2 * H1N + lane] + adst;
            e = e > 0.f ? e : 0.2f * e;
            m = fmaxf(m, e);
        }
    }
    float den = 0.f;
    for (int p = p0; p < p1; p++) {
        int s = g_CSRC[p];
        if (lane < H1N) {
            float e = g_ASD1[s * 2 * H1N + lane] + adst;
            e = e > 0.f ? e : 0.2f * e;
            den += expf(e - m);
        }
    }
    float rd = 1.f / (den + 1e-16f);
    float acc[H1N][3];
#pragma unroll
    for (int h = 0; h < H1N; h++) { acc[h][0] = 0.f; acc[h][1] = 0.f; acc[h][2] = 0.f; }
    for (int p = p0; p < p1; p++) {
        int s = g_CSRC[p];
        float al = 0.f;
        if (lane < H1N) {
            float e = g_ASD1[s * 2 * H1N + lane] + adst;
            e = e > 0.f ? e : 0.2f * e;
            al = expf(e - m) * rd;
        }
        const float* xr = &x[(size_t)s * F_IN];
        float xv0 = xr[lane];
        float xv1 = xr[32 + lane];
        float xv2 = (lane < F_IN - 64) ? xr[64 + lane] : 0.f;
#pragma unroll
        for (int h = 0; h < H1N; h++) {
            float a = __shfl_sync(0xffffffffu, al, h);
            acc[h][0] = fmaf(a, xv0, acc[h][0]);
            acc[h][1] = fmaf(a, xv1, acc[h][1]);
            acc[h][2] = fmaf(a, xv2, acc[h][2]);
        }
    }
    size_t base = (size_t)n * C1P;
#pragma unroll
    for (int h = 0; h < H1N; h++) {
        g_XAGG[base + h * 80 + lane] = acc[h][0];
        g_XAGG[base + h * 80 + 32 + lane] = acc[h][1];
        if (lane < F_IN - 64) g_XAGG[base + h * 80 + 64 + lane] = acc[h][2];
    }
}

// ---------------- TF32 GEMM: 64x128 tile, 8 warps, cp.async double-buffered --
#define PAp 20
#define PBp 136

__device__ __forceinline__ uint32_t f2tf32(float v) {
    uint32_t u;
    asm("cvt.rna.tf32.f32 %0, %1;" : "=r"(u) : "f"(v));
    return u;
}
__device__ __forceinline__ void cp16(uint32_t dst, const float* src, int nbytes) {
    asm volatile("cp.async.cg.shared.global [%0], [%1], 16, %2;\n"
                 :: "r"(dst), "l"(src), "r"(nbytes));
}

// act: 0 none, 1 relu, 2 elu. A rows may read past M (oversized/aligned buffers);
// B is zero-filled past K rows and N cols. C stores guarded.
__global__ void __launch_bounds__(256) k_mma3(
    const float* __restrict__ A_, const float* __restrict__ B_,
    const float* __restrict__ bias_, float* __restrict__ C_,
    int M, int K, int N, int lda, int ldb, int ldC, int act,
    long long stA, long long stB, long long stBias, long long stC,
    const float* __restrict__ attS_, const float* __restrict__ attD_,
    long long stAtt, float* __restrict__ outAS, float* __restrict__ outAD) {
    __shared__ __align__(16) float sA[2][64 * PAp];
    __shared__ __align__(16) float sB[2][16 * PBp];
    const float* A = A_ + (long long)blockIdx.z * stA;
    const float* B = B_ + (long long)blockIdx.z * stB;
    const float* bias = bias_ ? bias_ + (long long)blockIdx.z * stBias : nullptr;
    float* C = C_ + (long long)blockIdx.z * stC;
    const float* attS = attS_ ? attS_ + (long long)blockIdx.z * stAtt : nullptr;
    const float* attD = attD_ ? attD_ + (long long)blockIdx.z * stAtt : nullptr;

    int t = threadIdx.x;
    int warp = t >> 5, lane = t & 31;
    int g = lane >> 2, tg = lane & 3;
    int wm = warp >> 2, wn = warp & 3;
    int r0 = blockIdx.x * 64;
    int c0 = blockIdx.y * 128;

    // cp.async source indices
    int arow = t >> 2, acol = (t & 3) * 4;                  // 1 float4 for A
    const float* aptr = A + (size_t)(r0 + arow) * lda + acol;
    uint32_t sa_dst[2], sb_dst[2][2];
    sa_dst[0] = (uint32_t)__cvta_generic_to_shared(&sA[0][arow * PAp + acol]);
    sa_dst[1] = (uint32_t)__cvta_generic_to_shared(&sA[1][arow * PAp + acol]);
    int brow[2], bcol[2];
#pragma unroll
    for (int i = 0; i < 2; i++) {
        int id = t + i * 256;
        brow[i] = id >> 5;
        bcol[i] = (id & 31) * 4;
        sb_dst[0][i] = (uint32_t)__cvta_generic_to_shared(&sB[0][brow[i] * PBp + bcol[i]]);
        sb_dst[1][i] = (uint32_t)__cvta_generic_to_shared(&sB[1][brow[i] * PBp + bcol[i]]);
    }

    int niter = (K + 15) / 16;
    // prologue: stage 0
    {
        cp16(sa_dst[0], aptr, 16);
#pragma unroll
        for (int i = 0; i < 2; i++) {
            const float* src = B + (size_t)brow[i] * ldb + c0 + bcol[i];
            int nb = 0;
            if (brow[i] < K) {
                int v = N - (c0 + bcol[i]);
                nb = v >= 4 ? 16 : (v > 0 ? v * 4 : 0);
            }
            if (nb == 0) src = B;
            cp16(sb_dst[0][i], src, nb);
        }
        asm volatile("cp.async.commit_group;\n");
    }

    float acc[2][4][4];
#pragma unroll
    for (int mi = 0; mi < 2; mi++)
#pragma unroll
        for (int ni = 0; ni < 4; ni++)
#pragma unroll
            for (int r = 0; r < 4; r++) acc[mi][ni][r] = 0.f;

    for (int it = 0; it < niter; it++) {
        if (it + 1 < niter) {
            int kt = (it + 1) * 16;
            int buf = (it + 1) & 1;
            cp16(sa_dst[buf], aptr + kt, 16);
#pragma unroll
            for (int i = 0; i < 2; i++) {
                const float* src = B + (size_t)(kt + brow[i]) * ldb + c0 + bcol[i];
                int nb = 0;
                if (kt + brow[i] < K) {
                    int v = N - (c0 + bcol[i]);
                    nb = v >= 4 ? 16 : (v > 0 ? v * 4 : 0);
                }
                if (nb == 0) src = B;
                cp16(sb_dst[buf][i], src, nb);
            }
            asm volatile("cp.async.commit_group;\n");
            asm volatile("cp.async.wait_group 1;\n");
        } else {
            asm volatile("cp.async.wait_group 0;\n");
        }
        __syncthreads();
        int cb = it & 1;
#pragma unroll
        for (int kk = 0; kk < 16; kk += 8) {
            uint32_t af[2][4];
#pragma unroll
            for (int mi = 0; mi < 2; mi++) {
                int br = wm * 32 + mi * 16;
                af[mi][0] = f2tf32(sA[cb][(br + g) * PAp + kk + tg]);
                af[mi][1] = f2tf32(sA[cb][(br + g + 8) * PAp + kk + tg]);
                af[mi][2] = f2tf32(sA[cb][(br + g) * PAp + kk + tg + 4]);
                af[mi][3] = f2tf32(sA[cb][(br + g + 8) * PAp + kk + tg + 4]);
            }
            uint32_t bf[4][2];
#pragma unroll
            for (int ni = 0; ni < 4; ni++) {
                int bc = wn * 32 + ni * 8 + g;
                bf[ni][0] = f2tf32(sB[cb][(kk + tg) * PBp + bc]);
                bf[ni][1] = f2tf32(sB[cb][(kk + tg + 4) * PBp + bc]);
            }
#pragma unroll
            for (int mi = 0; mi < 2; mi++)
#pragma unroll
                for (int ni = 0; ni < 4; ni++) {
                    asm volatile(
                        "mma.sync.aligned.m16n8k8.row.col.f32.tf32.tf32.f32 "
                        "{%0,%1,%2,%3}, {%4,%5,%6,%7}, {%8,%9}, {%0,%1,%2,%3};\n"
                        : "+f"(acc[mi][ni][0]), "+f"(acc[mi][ni][1]),
                          "+f"(acc[mi][ni][2]), "+f"(acc[mi][ni][3])
                        : "r"(af[mi][0]), "r"(af[mi][1]), "r"(af[mi][2]), "r"(af[mi][3]),
                          "r"(bf[ni][0]), "r"(bf[ni][1]));
                }
        }
        __syncthreads();
    }
    // epilogue
#pragma unroll
    for (int mi = 0; mi < 2; mi++) {
#pragma unroll
        for (int half = 0; half < 2; half++) {
            int row = r0 + wm * 32 + mi * 16 + g + half * 8;
            float ps = 0.f, pd = 0.f;
#pragma unroll
            for (int ni = 0; ni < 4; ni++) {
                int col = c0 + wn * 32 + ni * 8 + tg * 2;
#pragma unroll
                for (int q = 0; q < 2; q++) {
                    if (row < M && col + q < N) {
                        float v = acc[mi][ni][half * 2 + q] + (bias ? bias[col + q] : 0.f);
                        if (act == 1) v = fmaxf(v, 0.f);
                        else if (act == 2) v = v > 0.f ? v : expm1f(v);
                        C[(size_t)row * ldC + col + q] = v;
                        if (attS) {
                            ps = fmaf(v, attS[col + q], ps);
                            pd = fmaf(v, attD[col + q], pd);
                        }
                    }
                }
            }
            if (attS) {
                ps += __shfl_xor_sync(0xffffffffu, ps, 1);
                ps += __shfl_xor_sync(0xffffffffu, ps, 2);
                pd += __shfl_xor_sync(0xffffffffu, pd, 1);
                pd += __shfl_xor_sync(0xffffffffu, pd, 2);
                if (tg == 0 && row < M) {
                    atomicAdd(&outAS[row], ps);
                    atomicAdd(&outAD[row], pd);
                }
            }
        }
    }
}

// ---------------- layer 2: fused softmax + aggregation + readout ------------
__global__ void k_agg2_w(const float* __restrict__ b2, const float* __restrict__ wg,
                         const float* __restrict__ bg, const int* __restrict__ batch) {
    int n = blockIdx.x * 8 + (threadIdx.x >> 5);
    if (n >= N_NODES) return;
    int lane = threadIdx.x & 31;
    int p0 = g_OFF[n], p1 = g_OFF[n + 1];
    float adst = g_AD2[n];
    float m = -1e30f;
    for (int p = p0; p < p1; p++) {
        float e = g_AS2[g_CSRC[p]] + adst;
        e = e > 0.f ? e : 0.2f * e;
        m = fmaxf(m, e);
    }
    float den = 0.f;
    for (int p = p0; p < p1; p++) {
        float e = g_AS2[g_CSRC[p]] + adst;
        e = e > 0.f ? e : 0.2f * e;
        den += expf(e - m);
    }
    float rd = 1.f / (den + 1e-16f);
    float a0 = 0.f, a1 = 0.f, a2 = 0.f, a3 = 0.f;
    for (int p = p0; p < p1; p++) {
        int s = g_CSRC[p];
        float e = g_AS2[s] + adst;
        e = e > 0.f ? e : 0.2f * e;
        float al = expf(e - m) * rd;
        const float* hr = &g_H2[(size_t)s * OUT2];
        a0 = fmaf(al, hr[lane], a0);
        a1 = fmaf(al, hr[32 + lane], a1);
        a2 = fmaf(al, hr[64 + lane], a2);
        a3 = fmaf(al, hr[96 + lane], a3);
    }
    float v0 = fmaxf(a0 + b2[lane], 0.f);
    float v1 = fmaxf(a1 + b2[32 + lane], 0.f);
    float v2 = fmaxf(a2 + b2[64 + lane], 0.f);
    float v3 = fmaxf(a3 + b2[96 + lane], 0.f);
    float gp = v0 * wg[lane] + v1 * wg[32 + lane] + v2 * wg[64 + lane] + v3 * wg[96 + lane];
#pragma unroll
    for (int o = 16; o > 0; o >>= 1) gp += __shfl_xor_sync(0xffffffffu, gp, o);
    float w = 1.f / (1.f + expf(-(gp + bg[0])));
    int gr = batch[n];
    float* hs = &g_HSUM[(size_t)gr * OUT2];
    float* hm = &g_HMAX[(size_t)gr * OUT2];
    atomicAdd(&hs[lane], v0 * w);
    atomicAdd(&hs[32 + lane], v1 * w);
    atomicAdd(&hs[64 + lane], v2 * w);
    atomicAdd(&hs[96 + lane], v3 * w);
    atomicMax((int*)&hm[lane], __float_as_int(v0));
    atomicMax((int*)&hm[32 + lane], __float_as_int(v1));
    atomicMax((int*)&hm[64 + lane], __float_as_int(v2));
    atomicMax((int*)&hm[96 + lane], __float_as_int(v3));
}

// ---------------- tail ------------------------------------------------------
__global__ void k_concat() {
    int i = blockIdx.x * blockDim.x + threadIdx.x;
    if (i >= N_GRAPHS * 512) return;
    int g = i / 512, c = i - g * 512;
    float v;
    if (c < 128)      v = g_HSUM[g * 128 + c];
    else if (c < 256) v = g_HMAX[g * 128 + (c - 128)];
    else              v = g_XT[g * 256 + (c - 256)];
    g_XC[i] = v;
}
__global__ void k_out(const float* __restrict__ Wo, const float* __restrict__ bo,
                      float* __restrict__ out) {
    int g = blockIdx.x, lane = threadIdx.x;
    float s = 0.f;
    for (int k = lane; k < 256; k += 32) s += g_X2[g * 256 + k] * Wo[k];
#pragma unroll
    for (int o = 16; o > 0; o >>= 1) s += __shfl_down_sync(0xffffffffu, s, o);
    if (lane == 0) out[g] = s + bo[0];
}

// ---------------- host ------------------------------------------------------
static inline dim3 mma_grid(int M, int N, int Z = 1) {
    return dim3((M + 63) / 64, (N + 127) / 128, Z);
}

extern "C" void kernel_launch(void* const* d_in, const int* in_sizes, int n_in,
                              void* d_out, int out_size) {
    const float* x      = (const float*)d_in[0];
    const int*   ei     = (const int*)d_in[1];
    const int*   batch  = (const int*)d_in[2];
    const float* target = (const float*)d_in[3];
    const float* W1  = (const float*)d_in[4];
    const float* as1 = (const float*)d_in[5];
    const float* ad1 = (const float*)d_in[6];
    const float* b1  = (const float*)d_in[7];
    const float* W2  = (const float*)d_in[8];
    const float* as2 = (const float*)d_in[9];
    const float* ad2 = (const float*)d_in[10];
    const float* b2  = (const float*)d_in[11];
    const float* wg  = (const float*)d_in[12];
    const float* bg  = (const float*)d_in[13];
    const float* Wxt = (const float*)d_in[14];
    const float* bxt = (const float*)d_in[15];
    const float* Wf1 = (const float*)d_in[16];
    const float* bf1 = (const float*)d_in[17];
    const float* Wf2 = (const float*)d_in[18];
    const float* bf2 = (const float*)d_in[19];
    const float* Wo  = (const float*)d_in[20];
    const float* bo  = (const float*)d_in[21];
    float* out = (float*)d_out;

    float *XAGG, *H1O, *H2, *W1P, *W2AS, *W2AD, *AS2, *AD2, *XT, *XC, *X1, *X2;
    cudaGetSymbolAddress((void**)&XAGG, g_XAGG);
    cudaGetSymbolAddress((void**)&H1O, g_H1O);
    cudaGetSymbolAddress((void**)&H2,  g_H2);
    cudaGetSymbolAddress((void**)&W1P, g_W1P);
    cudaGetSymbolAddress((void**)&W2AS, g_W2AS);
    cudaGetSymbolAddress((void**)&W2AD, g_W2AD);
    cudaGetSymbolAddress((void**)&AS2, g_AS2);
    cudaGetSymbolAddress((void**)&AD2, g_AD2);
    cudaGetSymbolAddress((void**)&XT,  g_XT);
    cudaGetSymbolAddress((void**)&XC,  g_XC);
    cudaGetSymbolAddress((void**)&X1,  g_X1);
    cudaGetSymbolAddress((void**)&X2,  g_X2);

    // CSR build + zero accumulators
    k_initdeg<<<(N_NODES + 255) / 256, 256>>>();
    k_hist<<<(N_EDGES + 255) / 256, 256>>>(ei);
    k_scan1<<<NB_SCAN, 1024>>>();
    k_scan2<<<1, 128>>>();
    k_scan3<<<(N_NODES + 255) / 256, 256>>>();
    k_scatter<<<(E_TOT + 255) / 256, 256>>>(ei);
    k_zero<<<(N_GRAPHS * OUT2 + 255) / 256, 256>>>();

    // weight prep
    k_prep_att<<<(F_IN * 2 * H1N + 255) / 256, 256>>>(W1, as1, ad1);
    k_prep_w1p<<<(F_IN * C1 + 255) / 256, 256>>>(W1);
    k_prep2v<<<(C1 + 255) / 256, 256>>>(W2, as2, ad2);

    // layer 1: logits -> fused softmax+agg -> batched GEMM (+att2 fold)
    k_att1<<<(N_NODES + 7) / 8, 256>>>(x);
    k_aggx_w<<<(N_NODES + 7) / 8, 256>>>(x);
    k_mma3<<<mma_grid(N_NODES, F_IN, H1N), 256>>>(
        XAGG, W1P, b1, H1O, N_NODES, F_IN, F_IN, C1P, C1P, C1, 2,
        80, 80, F_IN, F_IN,
        W2AS, W2AD, F_IN, AS2, AD2);

    // layer 2: H2 = H1O @ W2  [100000,780]x[780,128]
    k_mma3<<<mma_grid(N_NODES, OUT2), 256>>>(H1O, W2, nullptr, H2,
                                             N_NODES, C1, OUT2, C1, OUT2, OUT2, 0,
                                             0, 0, 0, 0, nullptr, nullptr, 0, nullptr, nullptr);
    k_agg2_w<<<(N_NODES + 7) / 8, 256>>>(b2, wg, bg, batch);

    // tail MLP
    k_mma3<<<mma_grid(N_GRAPHS, 256), 256>>>(target, Wxt, bxt, XT,
                                             N_GRAPHS, 1280, 256, 1280, 256, 256, 0,
                                             0, 0, 0, 0, nullptr, nullptr, 0, nullptr, nullptr);
    k_concat<<<(N_GRAPHS * 512 + 255) / 256, 256>>>();
    k_mma3<<<mma_grid(N_GRAPHS, 1024), 256>>>(XC, Wf1, bf1, X1,
                                              N_GRAPHS, 512, 1024, 512, 1024, 1024, 1,
                                              0, 0, 0, 0, nullptr, nullptr, 0, nullptr, nullptr);
    k_mma3<<<mma_grid(N_GRAPHS, 256), 256>>>(X1, Wf2, bf2, X2,
                                             N_GRAPHS, 1024, 256, 1024, 256, 256, 1,
                                             0, 0, 0, 0, nullptr, nullptr, 0, nullptr, nullptr);
    k_out<<<N_GRAPHS, 32>>>(Wo, bo, out);
}

// round 8
// speedup vs baseline: 3.0288x; 1.0007x over previous
#include <cuda_runtime.h>
#include <math.h>
#include <stdint.h>

#define N_NODES 100000
#define N_EDGES 400000
#define E_TOT   500000
#define N_GRAPHS 2048
#define F_IN 78
#define H1N 10
#define C1  780      // 10*78
#define C1P 800      // padded: 10 heads * 80
#define OUT2 128
#define NB_SCAN 98   // ceil(100000/1024)

// ---------------- scratch (device globals; no allocation allowed) -----------
__device__ __align__(16) float g_XAGG[N_NODES * C1P + 32 * C1P]; // padded pitch-80/head
__device__ __align__(16) float g_H1O[N_NODES * C1 + 32 * C1];
__device__ __align__(16) float g_H2[N_NODES * OUT2];
__device__ float g_ASD1[N_NODES * 2 * H1N];
__device__ float g_AS2[N_NODES], g_AD2[N_NODES];
__device__ int   g_DEG[N_NODES], g_INCL[N_NODES], g_BSUM[128], g_BOFF[128];
__device__ int   g_OFF[N_NODES + 1], g_CUR[N_NODES], g_CSRC[E_TOT];
__device__ float g_WATT[F_IN * 2 * H1N];
__device__ __align__(16) float g_W1P[F_IN * C1P];   // W1 re-laid to pitch 80/head
__device__ float g_W2AS[C1], g_W2AD[C1];
__device__ float g_HSUM[N_GRAPHS * OUT2], g_HMAX[N_GRAPHS * OUT2];
__device__ __align__(16) float g_XT[N_GRAPHS * 256];
__device__ __align__(16) float g_XC[N_GRAPHS * 512];
__device__ __align__(16) float g_X1[N_GRAPHS * 1024];
__device__ __align__(16) float g_X2[N_GRAPHS * 256];

// ---------------- CSR build -----------------------------------------------
__global__ void k_initdeg() {
    int i = blockIdx.x * blockDim.x + threadIdx.x;
    if (i < N_NODES) g_DEG[i] = 1;
}
__global__ void k_hist(const int* __restrict__ ei) {
    int e = blockIdx.x * blockDim.x + threadIdx.x;
    if (e < N_EDGES) atomicAdd(&g_DEG[ei[N_EDGES + e]], 1);
}
__global__ void k_scan1() {
    __shared__ int sw[32];
    int i = blockIdx.x * 1024 + threadIdx.x;
    int v = (i < N_NODES) ? g_DEG[i] : 0;
    int lane = threadIdx.x & 31, w = threadIdx.x >> 5;
    int x = v;
#pragma unroll
    for (int o = 1; o < 32; o <<= 1) {
        int y = __shfl_up_sync(0xffffffffu, x, o);
        if (lane >= o) x += y;
    }
    if (lane == 31) sw[w] = x;
    __syncthreads();
    if (w == 0) {
        int s = sw[lane];
#pragma unroll
        for (int o = 1; o < 32; o <<= 1) {
            int y = __shfl_up_sync(0xffffffffu, s, o);
            if (lane >= o) s += y;
        }
        sw[lane] = s;
    }
    __syncthreads();
    if (w > 0) x += sw[w - 1];
    if (i < N_NODES) g_INCL[i] = x;
    if (threadIdx.x == 1023) g_BSUM[blockIdx.x] = x;
}
__global__ void k_scan2() {
    __shared__ int sw[4];
    int t = threadIdx.x;
    int v = (t < NB_SCAN) ? g_BSUM[t] : 0;
    int lane = t & 31, w = t >> 5;
    int x = v;
#pragma unroll
    for (int o = 1; o < 32; o <<= 1) {
        int y = __shfl_up_sync(0xffffffffu, x, o);
        if (lane >= o) x += y;
    }
    if (lane == 31) sw[w] = x;
    __syncthreads();
    int add = 0;
    for (int i = 0; i < w; i++) add += sw[i];
    x += add;
    if (t < NB_SCAN) g_BOFF[t] = x - v;
}
__global__ void k_scan3() {
    int i = blockIdx.x * blockDim.x + threadIdx.x;
    if (i < N_NODES) {
        int off = g_INCL[i] - g_DEG[i] + g_BOFF[i >> 10];
        g_OFF[i] = off;
        g_CUR[i] = off;
        if (i == 0) g_OFF[N_NODES] = E_TOT;
    }
}
__global__ void k_scatter(const int* __restrict__ ei) {
    int i = blockIdx.x * blockDim.x + threadIdx.x;
    if (i >= E_TOT) return;
    int s, d;
    if (i < N_EDGES) { s = ei[i]; d = ei[N_EDGES + i]; }
    else             { s = d = i - N_EDGES; }
    int pos = atomicAdd(&g_CUR[d], 1);
    g_CSRC[pos] = s;
}

// ---------------- zero-init ----------------------------------------------
__global__ void k_zero() {
    int i = blockIdx.x * blockDim.x + threadIdx.x;
    if (i < N_GRAPHS * OUT2) { g_HSUM[i] = 0.f; g_HMAX[i] = 0.f; }
    if (i < N_NODES) { g_AS2[i] = 0.f; g_AD2[i] = 0.f; }
}

// ---------------- weight prep ----------------------------------------------
__global__ void k_prep_att(const float* __restrict__ W1, const float* __restrict__ as,
                           const float* __restrict__ ad) {
    int i = blockIdx.x * blockDim.x + threadIdx.x;
    if (i >= F_IN * 2 * H1N) return;
    int k = i / (2 * H1N), j = i - k * (2 * H1N);
    const float* a = (j < H1N) ? (as + j * F_IN) : (ad + (j - H1N) * F_IN);
    int h = (j < H1N) ? j : j - H1N;
    float s = 0.f;
    for (int d = 0; d < F_IN; d++) s += W1[k * C1 + h * F_IN + d] * a[d];
    g_WATT[i] = s;
}
__global__ void k_prep_w1p(const float* __restrict__ W1) {
    int i = blockIdx.x * blockDim.x + threadIdx.x;
    if (i >= F_IN * C1) return;
    int k = i / C1, c = i - k * C1;
    int h = c / F_IN, d = c - h * F_IN;
    g_W1P[k * C1P + h * 80 + d] = W1[i];
}
__global__ void k_prep2v(const float* __restrict__ W2, const float* __restrict__ as,
                         const float* __restrict__ ad) {
    int k = blockIdx.x * blockDim.x + threadIdx.x;
    if (k >= C1) return;
    float s = 0.f, t = 0.f;
    for (int d = 0; d < OUT2; d++) {
        float w = W2[k * OUT2 + d];
        s = fmaf(w, as[d], s);
        t = fmaf(w, ad[d], t);
    }
    g_W2AS[k] = s;
    g_W2AD[k] = t;
}

// ---------------- attention logits ------------------------------------------
__global__ void k_att1(const float* __restrict__ x) {
    __shared__ float sW[F_IN * 2 * H1N];
    __shared__ float sX[8 * F_IN];
    int tid = threadIdx.x, w = tid >> 5, lane = tid & 31;
    for (int i = tid; i < F_IN * 2 * H1N; i += 256) sW[i] = g_WATT[i];
    int n = blockIdx.x * 8 + w;
    if (n < N_NODES) {
        for (int d = lane; d < F_IN; d += 32) sX[w * F_IN + d] = x[(size_t)n * F_IN + d];
    }
    __syncthreads();
    if (n >= N_NODES || lane >= 2 * H1N) return;
    float s = 0.f;
    for (int d = 0; d < F_IN; d++)
        s = fmaf(sX[w * F_IN + d], sW[d * 2 * H1N + lane], s);
    g_ASD1[n * 2 * H1N + lane] = s;
}

// ---------------- layer 1: fused softmax + x-space aggregation (warp/node) --
__global__ void k_aggx_w(const float* __restrict__ x) {
    int n = blockIdx.x * 8 + (threadIdx.x >> 5);
    if (n >= N_NODES) return;
    int lane = threadIdx.x & 31;
    int p0 = g_OFF[n], p1 = g_OFF[n + 1];
    float adst = (lane < H1N) ? g_ASD1[n * 2 * H1N + H1N + lane] : 0.f;
    float m = -1e30f;
    for (int p = p0; p < p1; p++) {
        int s = g_CSRC[p];
        if (lane < H1N) {
            float e = g_ASD1[s * 2 * H1N + lane] + adst;
            e = e > 0.f ? e : 0.2f * e;
            m = fmaxf(m, e);
        }
    }
    float den = 0.f;
    for (int p = p0; p < p1; p++) {
        int s = g_CSRC[p];
        if (lane < H1N) {
            float e = g_ASD1[s * 2 * H1N + lane] + adst;
            e = e > 0.f ? e : 0.2f * e;
            den += expf(e - m);
        }
    }
    float rd = 1.f / (den + 1e-16f);
    float acc[H1N][3];
#pragma unroll
    for (int h = 0; h < H1N; h++) { acc[h][0] = 0.f; acc[h][1] = 0.f; acc[h][2] = 0.f; }
    for (int p = p0; p < p1; p++) {
        int s = g_CSRC[p];
        float al = 0.f;
        if (lane < H1N) {
            float e = g_ASD1[s * 2 * H1N + lane] + adst;
            e = e > 0.f ? e : 0.2f * e;
            al = expf(e - m) * rd;
        }
        const float* xr = &x[(size_t)s * F_IN];
        float xv0 = xr[lane];
        float xv1 = xr[32 + lane];
        float xv2 = (lane < F_IN - 64) ? xr[64 + lane] : 0.f;
#pragma unroll
        for (int h = 0; h < H1N; h++) {
            float a = __shfl_sync(0xffffffffu, al, h);
            acc[h][0] = fmaf(a, xv0, acc[h][0]);
            acc[h][1] = fmaf(a, xv1, acc[h][1]);
            acc[h][2] = fmaf(a, xv2, acc[h][2]);
        }
    }
    size_t base = (size_t)n * C1P;
#pragma unroll
    for (int h = 0; h < H1N; h++) {
        g_XAGG[base + h * 80 + lane] = acc[h][0];
        g_XAGG[base + h * 80 + 32 + lane] = acc[h][1];
        if (lane < F_IN - 64) g_XAGG[base + h * 80 + 64 + lane] = acc[h][2];
    }
}

// ---------------- TF32 GEMM: 64x128 tile, 8 warps, cp.async double-buffered --
#define PAp 20
#define PBp 136

__device__ __forceinline__ uint32_t f2tf32(float v) {
    uint32_t u;
    asm("cvt.rna.tf32.f32 %0, %1;" : "=r"(u) : "f"(v));
    return u;
}
__device__ __forceinline__ void cp16(uint32_t dst, const float* src, int nbytes) {
    asm volatile("cp.async.cg.shared.global [%0], [%1], 16, %2;\n"
                 :: "r"(dst), "l"(src), "r"(nbytes));
}

// act: 0 none, 1 relu, 2 elu. A rows may read past M (oversized/aligned buffers);
// B is zero-filled past K rows and N cols. C stores guarded.
__global__ void __launch_bounds__(256) k_mma3(
    const float* __restrict__ A_, const float* __restrict__ B_,
    const float* __restrict__ bias_, float* __restrict__ C_,
    int M, int K, int N, int lda, int ldb, int ldC, int act,
    long long stA, long long stB, long long stBias, long long stC,
    const float* __restrict__ attS_, const float* __restrict__ attD_,
    long long stAtt, float* __restrict__ outAS, float* __restrict__ outAD) {
    __shared__ __align__(16) float sA[2][64 * PAp];
    __shared__ __align__(16) float sB[2][16 * PBp];
    const float* A = A_ + (long long)blockIdx.z * stA;
    const float* B = B_ + (long long)blockIdx.z * stB;
    const float* bias = bias_ ? bias_ + (long long)blockIdx.z * stBias : nullptr;
    float* C = C_ + (long long)blockIdx.z * stC;
    const float* attS = attS_ ? attS_ + (long long)blockIdx.z * stAtt : nullptr;
    const float* attD = attD_ ? attD_ + (long long)blockIdx.z * stAtt : nullptr;

    int t = threadIdx.x;
    int warp = t >> 5, lane = t & 31;
    int g = lane >> 2, tg = lane & 3;
    int wm = warp >> 2, wn = warp & 3;
    int r0 = blockIdx.x * 64;
    int c0 = blockIdx.y * 128;

    // cp.async source indices
    int arow = t >> 2, acol = (t & 3) * 4;                  // 1 float4 for A
    const float* aptr = A + (size_t)(r0 + arow) * lda + acol;
    uint32_t sa_dst[2], sb_dst[2][2];
    sa_dst[0] = (uint32_t)__cvta_generic_to_shared(&sA[0][arow * PAp + acol]);
    sa_dst[1] = (uint32_t)__cvta_generic_to_shared(&sA[1][arow * PAp + acol]);
    int brow[2], bcol[2];
#pragma unroll
    for (int i = 0; i < 2; i++) {
        int id = t + i * 256;
        brow[i] = id >> 5;
        bcol[i] = (id & 31) * 4;
        sb_dst[0][i] = (uint32_t)__cvta_generic_to_shared(&sB[0][brow[i] * PBp + bcol[i]]);
        sb_dst[1][i] = (uint32_t)__cvta_generic_to_shared(&sB[1][brow[i] * PBp + bcol[i]]);
    }

    int niter = (K + 15) / 16;
    // prologue: stage 0
    {
        cp16(sa_dst[0], aptr, 16);
#pragma unroll
        for (int i = 0; i < 2; i++) {
            const float* src = B + (size_t)brow[i] * ldb + c0 + bcol[i];
            int nb = 0;
            if (brow[i] < K) {
                int v = N - (c0 + bcol[i]);
                nb = v >= 4 ? 16 : (v > 0 ? v * 4 : 0);
            }
            if (nb == 0) src = B;
            cp16(sb_dst[0][i], src, nb);
        }
        asm volatile("cp.async.commit_group;\n");
    }

    float acc[2][4][4];
#pragma unroll
    for (int mi = 0; mi < 2; mi++)
#pragma unroll
        for (int ni = 0; ni < 4; ni++)
#pragma unroll
            for (int r = 0; r < 4; r++) acc[mi][ni][r] = 0.f;

    for (int it = 0; it < niter; it++) {
        if (it + 1 < niter) {
            int kt = (it + 1) * 16;
            int buf = (it + 1) & 1;
            cp16(sa_dst[buf], aptr + kt, 16);
#pragma unroll
            for (int i = 0; i < 2; i++) {
                const float* src = B + (size_t)(kt + brow[i]) * ldb + c0 + bcol[i];
                int nb = 0;
                if (kt + brow[i] < K) {
                    int v = N - (c0 + bcol[i]);
                    nb = v >= 4 ? 16 : (v > 0 ? v * 4 : 0);
                }
                if (nb == 0) src = B;
                cp16(sb_dst[buf][i], src, nb);
            }
            asm volatile("cp.async.commit_group;\n");
            asm volatile("cp.async.wait_group 1;\n");
        } else {
            asm volatile("cp.async.wait_group 0;\n");
        }
        __syncthreads();
        int cb = it & 1;
#pragma unroll
        for (int kk = 0; kk < 16; kk += 8) {
            uint32_t af[2][4];
#pragma unroll
            for (int mi = 0; mi < 2; mi++) {
                int br = wm * 32 + mi * 16;
                af[mi][0] = f2tf32(sA[cb][(br + g) * PAp + kk + tg]);
                af[mi][1] = f2tf32(sA[cb][(br + g + 8) * PAp + kk + tg]);
                af[mi][2] = f2tf32(sA[cb][(br + g) * PAp + kk + tg + 4]);
                af[mi][3] = f2tf32(sA[cb][(br + g + 8) * PAp + kk + tg + 4]);
            }
            uint32_t bf[4][2];
#pragma unroll
            for (int ni = 0; ni < 4; ni++) {
                int bc = wn * 32 + ni * 8 + g;
                bf[ni][0] = f2tf32(sB[cb][(kk + tg) * PBp + bc]);
                bf[ni][1] = f2tf32(sB[cb][(kk + tg + 4) * PBp + bc]);
            }
#pragma unroll
            for (int mi = 0; mi < 2; mi++)
#pragma unroll
                for (int ni = 0; ni < 4; ni++) {
                    asm volatile(
                        "mma.sync.aligned.m16n8k8.row.col.f32.tf32.tf32.f32 "
                        "{%0,%1,%2,%3}, {%4,%5,%6,%7}, {%8,%9}, {%0,%1,%2,%3};\n"
                        : "+f"(acc[mi][ni][0]), "+f"(acc[mi][ni][1]),
                          "+f"(acc[mi][ni][2]), "+f"(acc[mi][ni][3])
                        : "r"(af[mi][0]), "r"(af[mi][1]), "r"(af[mi][2]), "r"(af[mi][3]),
                          "r"(bf[ni][0]), "r"(bf[ni][1]));
                }
        }
        __syncthreads();
    }
    // epilogue
#pragma unroll
    for (int mi = 0; mi < 2; mi++) {
#pragma unroll
        for (int half = 0; half < 2; half++) {
            int row = r0 + wm * 32 + mi * 16 + g + half * 8;
            float ps = 0.f, pd = 0.f;
#pragma unroll
            for (int ni = 0; ni < 4; ni++) {
                int col = c0 + wn * 32 + ni * 8 + tg * 2;
#pragma unroll
                for (int q = 0; q < 2; q++) {
                    if (row < M && col + q < N) {
                        float v = acc[mi][ni][half * 2 + q] + (bias ? bias[col + q] : 0.f);
                        if (act == 1) v = fmaxf(v, 0.f);
                        else if (act == 2) v = v > 0.f ? v : expm1f(v);
                        C[(size_t)row * ldC + col + q] = v;
                        if (attS) {
                            ps = fmaf(v, attS[col + q], ps);
                            pd = fmaf(v, attD[col + q], pd);
                        }
                    }
                }
            }
            if (attS) {
                ps += __shfl_xor_sync(0xffffffffu, ps, 1);
                ps += __shfl_xor_sync(0xffffffffu, ps, 2);
                pd += __shfl_xor_sync(0xffffffffu, pd, 1);
                pd += __shfl_xor_sync(0xffffffffu, pd, 2);
                if (tg == 0 && row < M) {
                    atomicAdd(&outAS[row], ps);
                    atomicAdd(&outAD[row], pd);
                }
            }
        }
    }
}

// ---------------- layer 2: fused softmax + aggregation + readout ------------
__global__ void k_agg2_w(const float* __restrict__ b2, const float* __restrict__ wg,
                         const float* __restrict__ bg, const int* __restrict__ batch) {
    int n = blockIdx.x * 8 + (threadIdx.x >> 5);
    if (n >= N_NODES) return;
    int lane = threadIdx.x & 31;
    int p0 = g_OFF[n], p1 = g_OFF[n + 1];
    float adst = g_AD2[n];
    float m = -1e30f;
    for (int p = p0; p < p1; p++) {
        float e = g_AS2[g_CSRC[p]] + adst;
        e = e > 0.f ? e : 0.2f * e;
        m = fmaxf(m, e);
    }
    float den = 0.f;
    for (int p = p0; p < p1; p++) {
        float e = g_AS2[g_CSRC[p]] + adst;
        e = e > 0.f ? e : 0.2f * e;
        den += expf(e - m);
    }
    float rd = 1.f / (den + 1e-16f);
    float a0 = 0.f, a1 = 0.f, a2 = 0.f, a3 = 0.f;
    for (int p = p0; p < p1; p++) {
        int s = g_CSRC[p];
        float e = g_AS2[s] + adst;
        e = e > 0.f ? e : 0.2f * e;
        float al = expf(e - m) * rd;
        const float* hr = &g_H2[(size_t)s * OUT2];
        a0 = fmaf(al, hr[lane], a0);
        a1 = fmaf(al, hr[32 + lane], a1);
        a2 = fmaf(al, hr[64 + lane], a2);
        a3 = fmaf(al, hr[96 + lane], a3);
    }
    float v0 = fmaxf(a0 + b2[lane], 0.f);
    float v1 = fmaxf(a1 + b2[32 + lane], 0.f);
    float v2 = fmaxf(a2 + b2[64 + lane], 0.f);
    float v3 = fmaxf(a3 + b2[96 + lane], 0.f);
    float gp = v0 * wg[lane] + v1 * wg[32 + lane] + v2 * wg[64 + lane] + v3 * wg[96 + lane];
#pragma unroll
    for (int o = 16; o > 0; o >>= 1) gp += __shfl_xor_sync(0xffffffffu, gp, o);
    float w = 1.f / (1.f + expf(-(gp + bg[0])));
    int gr = batch[n];
    float* hs = &g_HSUM[(size_t)gr * OUT2];
    float* hm = &g_HMAX[(size_t)gr * OUT2];
    atomicAdd(&hs[lane], v0 * w);
    atomicAdd(&hs[32 + lane], v1 * w);
    atomicAdd(&hs[64 + lane], v2 * w);
    atomicAdd(&hs[96 + lane], v3 * w);
    atomicMax((int*)&hm[lane], __float_as_int(v0));
    atomicMax((int*)&hm[32 + lane], __float_as_int(v1));
    atomicMax((int*)&hm[64 + lane], __float_as_int(v2));
    atomicMax((int*)&hm[96 + lane], __float_as_int(v3));
}

// ---------------- tail ------------------------------------------------------
__global__ void k_concat() {
    int i = blockIdx.x * blockDim.x + threadIdx.x;
    if (i >= N_GRAPHS * 512) return;
    int g = i / 512, c = i - g * 512;
    float v;
    if (c < 128)      v = g_HSUM[g * 128 + c];
    else if (c < 256) v = g_HMAX[g * 128 + (c - 128)];
    else              v = g_XT[g * 256 + (c - 256)];
    g_XC[i] = v;
}
__global__ void k_out(const float* __restrict__ Wo, const float* __restrict__ bo,
                      float* __restrict__ out) {
    int g = blockIdx.x, lane = threadIdx.x;
    float s = 0.f;
    for (int k = lane; k < 256; k += 32) s += g_X2[g * 256 + k] * Wo[k];
#pragma unroll
    for (int o = 16; o > 0; o >>= 1) s += __shfl_down_sync(0xffffffffu, s, o);
    if (lane == 0) out[g] = s + bo[0];
}

// ---------------- host ------------------------------------------------------
static inline dim3 mma_grid(int M, int N, int Z = 1) {
    return dim3((M + 63) / 64, (N + 127) / 128, Z);
}

extern "C" void kernel_launch(void* const* d_in, const int* in_sizes, int n_in,
                              void* d_out, int out_size) {
    const float* x      = (const float*)d_in[0];
    const int*   ei     = (const int*)d_in[1];
    const int*   batch  = (const int*)d_in[2];
    const float* target = (const float*)d_in[3];
    const float* W1  = (const float*)d_in[4];
    const float* as1 = (const float*)d_in[5];
    const float* ad1 = (const float*)d_in[6];
    const float* b1  = (const float*)d_in[7];
    const float* W2  = (const float*)d_in[8];
    const float* as2 = (const float*)d_in[9];
    const float* ad2 = (const float*)d_in[10];
    const float* b2  = (const float*)d_in[11];
    const float* wg  = (const float*)d_in[12];
    const float* bg  = (const float*)d_in[13];
    const float* Wxt = (const float*)d_in[14];
    const float* bxt = (const float*)d_in[15];
    const float* Wf1 = (const float*)d_in[16];
    const float* bf1 = (const float*)d_in[17];
    const float* Wf2 = (const float*)d_in[18];
    const float* bf2 = (const float*)d_in[19];
    const float* Wo  = (const float*)d_in[20];
    const float* bo  = (const float*)d_in[21];
    float* out = (float*)d_out;

    float *XAGG, *H1O, *H2, *W1P, *W2AS, *W2AD, *AS2, *AD2, *XT, *XC, *X1, *X2;
    cudaGetSymbolAddress((void**)&XAGG, g_XAGG);
    cudaGetSymbolAddress((void**)&H1O, g_H1O);
    cudaGetSymbolAddress((void**)&H2,  g_H2);
    cudaGetSymbolAddress((void**)&W1P, g_W1P);
    cudaGetSymbolAddress((void**)&W2AS, g_W2AS);
    cudaGetSymbolAddress((void**)&W2AD, g_W2AD);
    cudaGetSymbolAddress((void**)&AS2, g_AS2);
    cudaGetSymbolAddress((void**)&AD2, g_AD2);
    cudaGetSymbolAddress((void**)&XT,  g_XT);
    cudaGetSymbolAddress((void**)&XC,  g_XC);
    cudaGetSymbolAddress((void**)&X1,  g_X1);
    cudaGetSymbolAddress((void**)&X2,  g_X2);

    // CSR build + zero accumulators
    k_initdeg<<<(N_NODES + 255) / 256, 256>>>();
    k_hist<<<(N_EDGES + 255) / 256, 256>>>(ei);
    k_scan1<<<NB_SCAN, 1024>>>();
    k_scan2<<<1, 128>>>();
    k_scan3<<<(N_NODES + 255) / 256, 256>>>();
    k_scatter<<<(E_TOT + 255) / 256, 256>>>(ei);
    k_zero<<<(N_GRAPHS * OUT2 + 255) / 256, 256>>>();

    // weight prep
    k_prep_att<<<(F_IN * 2 * H1N + 255) / 256, 256>>>(W1, as1, ad1);
    k_prep_w1p<<<(F_IN * C1 + 255) / 256, 256>>>(W1);
    k_prep2v<<<(C1 + 255) / 256, 256>>>(W2, as2, ad2);

    // layer 1: logits -> fused softmax+agg -> batched GEMM (+att2 fold)
    k_att1<<<(N_NODES + 7) / 8, 256>>>(x);
    k_aggx_w<<<(N_NODES + 7) / 8, 256>>>(x);
    k_mma3<<<mma_grid(N_NODES, F_IN, H1N), 256>>>(
        XAGG, W1P, b1, H1O, N_NODES, F_IN, F_IN, C1P, C1P, C1, 2,
        80, 80, F_IN, F_IN,
        W2AS, W2AD, F_IN, AS2, AD2);

    // layer 2: H2 = H1O @ W2  [100000,780]x[780,128]
    k_mma3<<<mma_grid(N_NODES, OUT2), 256>>>(H1O, W2, nullptr, H2,
                                             N_NODES, C1, OUT2, C1, OUT2, OUT2, 0,
                                             0, 0, 0, 0, nullptr, nullptr, 0, nullptr, nullptr);
    k_agg2_w<<<(N_NODES + 7) / 8, 256>>>(b2, wg, bg, batch);

    // tail MLP
    k_mma3<<<mma_grid(N_GRAPHS, 256), 256>>>(target, Wxt, bxt, XT,
                                             N_GRAPHS, 1280, 256, 1280, 256, 256, 0,
                                             0, 0, 0, 0, nullptr, nullptr, 0, nullptr, nullptr);
    k_concat<<<(N_GRAPHS * 512 + 255) / 256, 256>>>();
    k_mma3<<<mma_grid(N_GRAPHS, 1024), 256>>>(XC, Wf1, bf1, X1,
                                              N_GRAPHS, 512, 1024, 512, 1024, 1024, 1,
                                              0, 0, 0, 0, nullptr, nullptr, 0, nullptr, nullptr);
    k_mma3<<<mma_grid(N_GRAPHS, 256), 256>>>(X1, Wf2, bf2, X2,
                                             N_GRAPHS, 1024, 256, 1024, 256, 256, 1,
                                             0, 0, 0, 0, nullptr, nullptr, 0, nullptr, nullptr);
    k_out<<<N_GRAPHS, 32>>>(Wo, bo, out);
}